// round 13
// baseline (speedup 1.0000x reference)
#include <cuda_runtime.h>
#include <cuda_bf16.h>
#include <cstdint>
#include <cstddef>

#define THREADS 512

// Packed pre-swizzled bf16 hi/lo weights:
// sw blocks: per (layer, ntile, kchunk64, sub): 32KB = [hi 16KB | lo 16KB]
// bw blocks: per (layer, ntile, kchunk64): 32KB
__device__ __align__(128) char g_swp[167772160];   // 160MB
__device__ __align__(128) char g_bwp[20971520];    // 20MB
// Packed A-block regions (ping-pong across layers):
// per (mtile, kchunk64, sub 0..8): 32KB; sub 0..7 basis tiles, sub 8 x tile.
__device__ __align__(128) char g_ab0[301989888];   // L0-in (I=1024) / L2-in (I=256)
__device__ __align__(128) char g_ab1[603979776];   // L1-in / L3-in (I=2048)

// Gaussian basis recurrence: e_g = e0 * u^g * exp(-2e-4*g^2)
__constant__ float RAT[7] = {0.99980002f, 0.99940018f, 0.99900050f,
                             0.99860098f, 0.99820162f, 0.99780242f, 0.99740338f};

// ---------------- threefry2x32 (JAX-compatible, validated) ----------------
__device__ __forceinline__ uint32_t rotl32d(uint32_t v, int d) {
    return __funnelshift_l(v, v, d);
}
__device__ __forceinline__ void threefry2x32_dev(uint32_t k0, uint32_t k1,
                                                 uint32_t c0, uint32_t c1,
                                                 uint32_t& o0, uint32_t& o1) {
    uint32_t ks2 = k0 ^ k1 ^ 0x1BD11BDAu;
    uint32_t x0 = c0 + k0, x1 = c1 + k1;
#define TF_RND(r) { x0 += x1; x1 = rotl32d(x1, r); x1 ^= x0; }
    TF_RND(13) TF_RND(15) TF_RND(26) TF_RND(6)
    x0 += k1;  x1 += ks2 + 1u;
    TF_RND(17) TF_RND(29) TF_RND(16) TF_RND(24)
    x0 += ks2; x1 += k0 + 2u;
    TF_RND(13) TF_RND(15) TF_RND(26) TF_RND(6)
    x0 += k0;  x1 += k1 + 3u;
    TF_RND(17) TF_RND(29) TF_RND(16) TF_RND(24)
    x0 += k1;  x1 += ks2 + 4u;
    TF_RND(13) TF_RND(15) TF_RND(26) TF_RND(6)
    x0 += ks2; x1 += k0 + 5u;
#undef TF_RND
    o0 = x0; o1 = x1;
}
static inline uint32_t rotl32h(uint32_t v, int d) {
    return (v << d) | (v >> (32 - d));
}
static void threefry2x32_host(uint32_t k0, uint32_t k1, uint32_t c0, uint32_t c1,
                              uint32_t& o0, uint32_t& o1) {
    uint32_t ks2 = k0 ^ k1 ^ 0x1BD11BDAu;
    uint32_t x0 = c0 + k0, x1 = c1 + k1;
#define TF_RND(r) { x0 += x1; x1 = rotl32h(x1, r); x1 ^= x0; }
    TF_RND(13) TF_RND(15) TF_RND(26) TF_RND(6)
    x0 += k1;  x1 += ks2 + 1u;
    TF_RND(17) TF_RND(29) TF_RND(16) TF_RND(24)
    x0 += ks2; x1 += k0 + 2u;
    TF_RND(13) TF_RND(15) TF_RND(26) TF_RND(6)
    x0 += k0;  x1 += k1 + 3u;
    TF_RND(17) TF_RND(29) TF_RND(16) TF_RND(24)
    x0 += k1;  x1 += ks2 + 4u;
    TF_RND(13) TF_RND(15) TF_RND(26) TF_RND(6)
    x0 += ks2; x1 += k0 + 5u;
#undef TF_RND
    o0 = x0; o1 = x1;
}

// ---------------- helpers ----------------
__device__ __forceinline__ uint32_t smem_u32(const void* p) {
    uint32_t a;
    asm("{ .reg .u64 t; cvta.to.shared.u64 t, %1; cvt.u32.u64 %0, t; }"
        : "=r"(a) : "l"(p));
    return a;
}
#define SW128(o) ((o) ^ ((((uint32_t)(o)) >> 3) & 0x70))

#define LDSM4(rv, a) \
    asm volatile("ldmatrix.sync.aligned.m8n8.x4.shared.b16 {%0,%1,%2,%3}, [%4];" \
        : "=r"((rv)[0]), "=r"((rv)[1]), "=r"((rv)[2]), "=r"((rv)[3]) \
        : "r"(a))

#define MMA_BF16(c, a, b0, b1) \
    asm volatile("mma.sync.aligned.m16n8k16.row.col.f32.bf16.bf16.f32 " \
        "{%0,%1,%2,%3}, {%4,%5,%6,%7}, {%8,%9}, {%0,%1,%2,%3};" \
        : "+f"((c)[0]), "+f"((c)[1]), "+f"((c)[2]), "+f"((c)[3]) \
        : "r"((a)[0]), "r"((a)[1]), "r"((a)[2]), "r"((a)[3]), "r"(b0), "r"(b1))

#define CP_ASYNC16(dst, src) \
    asm volatile("cp.async.cg.shared.global [%0], [%1], 16;" \
                 :: "r"((uint32_t)(dst)), "l"(src) : "memory")
#define CP_COMMIT() asm volatile("cp.async.commit_group;" ::: "memory")
#define CP_WAIT0()  asm volatile("cp.async.wait_group 0;" ::: "memory")
#define CP_WAIT1()  asm volatile("cp.async.wait_group 1;" ::: "memory")

__device__ __forceinline__ void bfsplit2(float a, float b, uint32_t& hi2, uint32_t& lo2) {
    asm("cvt.rn.bf16x2.f32 %0, %1, %2;" : "=r"(hi2) : "f"(b), "f"(a));
    __nv_bfloat162 hv = *reinterpret_cast<__nv_bfloat162*>(&hi2);
    float ra = a - __bfloat162float(hv.x);
    float rb = b - __bfloat162float(hv.y);
    asm("cvt.rn.bf16x2.f32 %0, %1, %2;" : "=r"(lo2) : "f"(rb), "f"(ra));
}

// ---------------- pack kernels ----------------
__global__ void pack_sw_kernel(const float* __restrict__ sw, char* __restrict__ dst,
                               int I, int O) {
    size_t idx = (size_t)blockIdx.x * blockDim.x + threadIdx.x;
    size_t total = (size_t)I * O * 4;
    if (idx >= total) return;
    int g2 = (int)(idx & 3) * 2;
    size_t rem = idx >> 2;
    int o = (int)(rem % O);
    int i = (int)(rem / O);
    float2 wv = *reinterpret_cast<const float2*>(&sw[((size_t)i * O + o) * 8 + g2]);
    uint32_t hw, lw;
    bfsplit2(wv.x, wv.y, hw, lw);
    int t = o >> 7, n = o & 127, c = i >> 6, s = (i >> 3) & 7, ii = i & 7;
    size_t blk = (((size_t)t * (I >> 6) + c) * 8 + s) * 32768;
    uint32_t off = SW128((uint32_t)(n * 128 + (ii * 8 + g2) * 2));
    *reinterpret_cast<uint32_t*>(dst + blk + off) = hw;
    *reinterpret_cast<uint32_t*>(dst + blk + 16384 + off) = lw;
}

__global__ void pack_bw_kernel(const float* __restrict__ bw, char* __restrict__ dst,
                               int I, int O) {
    size_t idx = (size_t)blockIdx.x * blockDim.x + threadIdx.x;
    size_t total = (size_t)O * (I >> 1);
    if (idx >= total) return;
    int o = (int)(idx % O);
    int kp = (int)(idx / O);
    float b0 = bw[(size_t)(2 * kp) * O + o];
    float b1 = bw[(size_t)(2 * kp + 1) * O + o];
    uint32_t hw, lw;
    bfsplit2(b0, b1, hw, lw);
    int t = o >> 7, n = o & 127;
    int c = (2 * kp) >> 6, klocal = (2 * kp) & 63;
    size_t blk = ((size_t)t * (I >> 6) + c) * 32768;
    uint32_t off = SW128((uint32_t)(n * 128 + klocal * 2));
    *reinterpret_cast<uint32_t*>(dst + blk + off) = hw;
    *reinterpret_cast<uint32_t*>(dst + blk + 16384 + off) = lw;
}

// basis tiles from fp32 activations (L0 only)
__global__ void pack_bases_kernel(const float* __restrict__ act,
                                  char* __restrict__ ab, int I, int nkc) {
    int bid = blockIdx.x;
    int sub = bid & 7;
    int t = bid >> 3;
    int kc = t % nkc;
    int mt = t / nkc;
    char* blk = ab + (((size_t)mt * nkc + kc) * 9 + sub) * 32768;
    int tid = threadIdx.x;
    #pragma unroll
    for (int rr = 0; rr < 4; ++rr) {
        int v = rr * 256 + tid;
        int mloc = v >> 3, il = v & 7;
        float xv = act[(size_t)(mt * 128 + mloc) * I + kc * 64 + sub * 8 + il];
        float d = xv + 0.044f;
        float e = __expf(-3.125f * d * d);
        float u = __expf(0.05f * d);
        float vv[8];
        vv[0] = e;
        #pragma unroll
        for (int g = 1; g < 8; ++g) vv[g] = vv[g - 1] * u * RAT[g - 1];
        uint32_t hw[4], lw[4];
        #pragma unroll
        for (int qq = 0; qq < 4; ++qq)
            bfsplit2(vv[2 * qq], vv[2 * qq + 1], hw[qq], lw[qq]);
        uint32_t off = SW128((uint32_t)(mloc * 128 + il * 16));
        *reinterpret_cast<uint4*>(blk + off) = make_uint4(hw[0], hw[1], hw[2], hw[3]);
        *reinterpret_cast<uint4*>(blk + 16384 + off) = make_uint4(lw[0], lw[1], lw[2], lw[3]);
    }
}

// basis tiles from packed x-blocks written by the previous layer's epilogue
__global__ void pack_bases_pk_kernel(char* __restrict__ ab, int nkc) {
    int bid = blockIdx.x;
    int sub = bid & 7;
    int t = bid >> 3;
    int kc = t % nkc;
    int mt = t / nkc;
    char* base9 = ab + ((size_t)mt * nkc + kc) * 9 * 32768;
    const char* xblk = base9 + 8 * 32768;
    char* blk = base9 + sub * 32768;
    int tid = threadIdx.x;
    #pragma unroll
    for (int rr = 0; rr < 4; ++rr) {
        int v = rr * 256 + tid;
        int mloc = v >> 3, il = v & 7;
        uint32_t xoff = SW128((uint32_t)(mloc * 128 + (sub * 8 + il) * 2));
        float xh = __bfloat162float(
            *reinterpret_cast<const __nv_bfloat16*>(xblk + xoff));
        float xl = __bfloat162float(
            *reinterpret_cast<const __nv_bfloat16*>(xblk + 16384 + xoff));
        float xv = xh + xl;
        float d = xv + 0.044f;
        float e = __expf(-3.125f * d * d);
        float u = __expf(0.05f * d);
        float vv[8];
        vv[0] = e;
        #pragma unroll
        for (int g = 1; g < 8; ++g) vv[g] = vv[g - 1] * u * RAT[g - 1];
        uint32_t hw[4], lw[4];
        #pragma unroll
        for (int qq = 0; qq < 4; ++qq)
            bfsplit2(vv[2 * qq], vv[2 * qq + 1], hw[qq], lw[qq]);
        uint32_t off = SW128((uint32_t)(mloc * 128 + il * 16));
        *reinterpret_cast<uint4*>(blk + off) = make_uint4(hw[0], hw[1], hw[2], hw[3]);
        *reinterpret_cast<uint4*>(blk + 16384 + off) = make_uint4(lw[0], lw[1], lw[2], lw[3]);
    }
}

// x tiles from fp32 input (L0 only)
__global__ void pack_x_kernel(const float* __restrict__ act,
                              char* __restrict__ ab, int I, int nkc) {
    int bid = blockIdx.x;
    int kc = bid % nkc;
    int mt = bid / nkc;
    char* blk = ab + (((size_t)mt * nkc + kc) * 9 + 8) * 32768;
    int tid = threadIdx.x;
    #pragma unroll
    for (int rr = 0; rr < 8; ++rr) {
        int v = rr * 256 + tid;
        int mloc = v >> 4, c4 = v & 15;
        float4 xv = *reinterpret_cast<const float4*>(
            &act[(size_t)(mt * 128 + mloc) * I + kc * 64 + c4 * 4]);
        uint32_t h0w, l0w, h1w, l1w;
        bfsplit2(xv.x, xv.y, h0w, l0w);
        bfsplit2(xv.z, xv.w, h1w, l1w);
        uint32_t off = SW128((uint32_t)(mloc * 128 + c4 * 8));
        *reinterpret_cast<uint2*>(blk + off) = make_uint2(h0w, h1w);
        *reinterpret_cast<uint2*>(blk + 16384 + off) = make_uint2(l0w, l1w);
    }
}

// ---------------- SMEM: 3-stage ring, 64KB per stage ----------------
static constexpr int STAGE_STRIDE = 65536;
static constexpr int NSTAGE = 3;
static constexpr int SMEM_SZ = NSTAGE * STAGE_STRIDE;   // 192KB
static constexpr int SMEM_DYN = SMEM_SZ + 1024;

// ---------------- main kernel: R11 mainloop + x-write epilogue ----------------
__global__ __launch_bounds__(THREADS, 1)
void kan_mma_kernel(const char* __restrict__ ab,
                    const char* __restrict__ swp,
                    const char* __restrict__ bwp,
                    const float* __restrict__ sbp,
                    const float* __restrict__ ssp,
                    const float* __restrict__ snp,
                    float* __restrict__ outp,      // may be null
                    char* __restrict__ next_ab,    // may be null
                    int nkc, int O,
                    uint32_t nk0, uint32_t nk1) {
    extern __shared__ char raw[];
    const uint32_t rawu = smem_u32(raw);
    const uint32_t sbase = (rawu + 1023u) & ~1023u;

    const int tid = threadIdx.x;
    const int wid = tid >> 5;
    const int lid = tid & 31;
    const int wm  = wid >> 2;
    const int wn  = wid & 3;
    const int m0  = blockIdx.y * 128;
    const int n0  = blockIdx.x * 128;   // n fastest
    const int mt  = blockIdx.y;
    const int nnkc = O >> 6;            // next layer's k-chunk count

    const int q = lid >> 3, r = lid & 7;
    const int rowA_l = r + (q & 1) * 8;
    const int kselA  = (q >> 1) * 16;
    const int rowB_l = r + (q >> 1) * 8;
    const int kselB  = (q & 1) * 16;

    float accS[2][4][4];
    float accB[2][4][4];
    #pragma unroll
    for (int a = 0; a < 2; ++a)
        #pragma unroll
        for (int b = 0; b < 4; ++b)
            #pragma unroll
            for (int e = 0; e < 4; ++e) { accS[a][b][e] = 0.f; accB[a][b][e] = 0.f; }

    const size_t a_tile = (size_t)mt * nkc;
    const size_t b_tile = (size_t)(n0 >> 7) * nkc;
    const int total = nkc * 9;

    auto issue_stage = [&](int s) {
        int kc = s / 9, sub = s - kc * 9;
        uint32_t dst = sbase + (s % NSTAGE) * STAGE_STRIDE;
        const char* asrc = ab + ((a_tile + kc) * 9 + sub) * 32768;
        const char* bsrc = (sub < 8)
            ? swp + (((b_tile + kc) * 8) + sub) * 32768
            : bwp + (b_tile + kc) * 32768;
        #pragma unroll
        for (int rr = 0; rr < 4; ++rr) {
            uint32_t off = (uint32_t)(rr * THREADS + tid) * 16;
            CP_ASYNC16(dst + off, asrc + off);
        }
        #pragma unroll
        for (int rr = 0; rr < 4; ++rr) {
            uint32_t off = (uint32_t)(rr * THREADS + tid) * 16;
            CP_ASYNC16(dst + 32768 + off, bsrc + off);
        }
        CP_COMMIT();
    };

    auto do_mma = [&](int buf, float (&acc)[2][4][4]) {
        const uint32_t Ah = sbase + buf * STAGE_STRIDE;
        const uint32_t Al = Ah + 16384;
        const uint32_t Bh = Ah + 32768;
        const uint32_t Bl = Ah + 49152;
        #pragma unroll
        for (int k16 = 0; k16 < 4; ++k16) {
            const int kbyt = k16 * 32;
            uint32_t ah[2][4], al[2][4];
            #pragma unroll
            for (int mf = 0; mf < 2; ++mf) {
                int m = wm * 32 + mf * 16 + rowA_l;
                uint32_t off = (uint32_t)(m * 128)
                             + (((uint32_t)(kbyt + kselA)) ^ ((m * 16) & 0x70));
                LDSM4(ah[mf], Ah + off);
                LDSM4(al[mf], Al + off);
            }
            uint32_t bh[2][4], bl[2][4];
            #pragma unroll
            for (int nb = 0; nb < 2; ++nb) {
                int n = wn * 32 + nb * 16 + rowB_l;
                uint32_t off = (uint32_t)(n * 128)
                             + (((uint32_t)(kbyt + kselB)) ^ ((n * 16) & 0x70));
                LDSM4(bh[nb], Bh + off);
                LDSM4(bl[nb], Bl + off);
            }
            #pragma unroll
            for (int mf = 0; mf < 2; ++mf)
                #pragma unroll
                for (int nf = 0; nf < 4; ++nf) {
                    const int nb = nf >> 1, ri = (nf & 1) * 2;
                    MMA_BF16(acc[mf][nf], ah[mf], bh[nb][ri], bh[nb][ri + 1]);
                    MMA_BF16(acc[mf][nf], ah[mf], bl[nb][ri], bl[nb][ri + 1]);
                    MMA_BF16(acc[mf][nf], al[mf], bh[nb][ri], bh[nb][ri + 1]);
                }
        }
    };

    issue_stage(0);
    issue_stage(1);
    for (int s = 0; s < total; ++s) {
        if (s < total - 1) { CP_WAIT1(); } else { CP_WAIT0(); }
        __syncthreads();
        int sub = s % 9;
        if (sub == 8) do_mma(s % NSTAGE, accB);
        else          do_mma(s % NSTAGE, accS);
        if (s + 2 < total) issue_stage(s + 2);   // R7/R11 order: issue AFTER mma
    }

    // ---------------- epilogue: fp32 out and/or packed next-layer x tiles ------
    const float snv = *snp;
    const int rq = lid >> 2, cq = (lid & 3) * 2;
    #pragma unroll
    for (int mf = 0; mf < 2; ++mf) {
        #pragma unroll
        for (int nf = 0; nf < 4; ++nf) {
            #pragma unroll
            for (int half = 0; half < 2; ++half) {
                int mloc = wm * 32 + mf * 16 + rq + half * 8;
                int b = m0 + mloc;
                int obase = n0 + wn * 32 + nf * 8 + cq;
                float vals[2];
                #pragma unroll
                for (int e = 0; e < 2; ++e) {
                    int o = obase + e;
                    float sv = accS[mf][nf][half * 2 + e];
                    float bv = accB[mf][nf][half * 2 + e];
                    float sg = 1.0f / (1.0f + __expf(-bv));
                    uint32_t li = (uint32_t)b * (uint32_t)O + (uint32_t)o;
                    uint32_t r0, r1;
                    threefry2x32_dev(nk0, nk1, 0u, li, r0, r1);
                    uint32_t bits = r0 ^ r1;
                    float f = __uint_as_float((bits >> 9) | 0x3f800000u) - 1.0f;
                    float uu = fmaxf(-0.99999994f, fmaf(f, 2.0f, -0.99999994f));
                    float nz = 1.41421356f * erfinvf(uu);
                    vals[e] = bv * sg * sbp[o] + sv * ssp[o] + nz * snv;
                }
                if (outp) {
                    *reinterpret_cast<float2*>(&outp[(size_t)b * O + obase]) =
                        make_float2(vals[0], vals[1]);
                }
                if (next_ab) {
                    int kc = obase >> 6;
                    char* xblk = next_ab
                        + (((size_t)mt * nnkc + kc) * 9 + 8) * 32768;
                    uint32_t xh, xl;
                    bfsplit2(vals[0], vals[1], xh, xl);
                    uint32_t offx = SW128((uint32_t)(mloc * 128 + (obase & 63) * 2));
                    *reinterpret_cast<uint32_t*>(xblk + offx) = xh;
                    *reinterpret_cast<uint32_t*>(xblk + 16384 + offx) = xl;
                }
            }
        }
    }
}

// ---------------- launch ----------------
extern "C" void kernel_launch(void* const* d_in, const int* in_sizes, int n_in,
                              void* d_out, int out_size) {
    const float* x = (const float*)d_in[0];
    const float* sw[4]; const float* bw[4]; const float* sb[4];
    const float* ss[4]; const float* sn[4];
    for (int li = 0; li < 4; ++li) {
        sw[li] = (const float*)d_in[1 + 5 * li + 0];
        bw[li] = (const float*)d_in[1 + 5 * li + 1];
        sb[li] = (const float*)d_in[1 + 5 * li + 2];
        ss[li] = (const float*)d_in[1 + 5 * li + 3];
        sn[li] = (const float*)d_in[1 + 5 * li + 4];
    }
    const int B = in_sizes[0] / 1024;   // 8192
    float* out  = (float*)d_out;
    float* xrec = out;
    float* z    = out + (size_t)B * 1024;

    char* swp; cudaGetSymbolAddress((void**)&swp, g_swp);
    char* bwp; cudaGetSymbolAddress((void**)&bwp, g_bwp);
    char* ab0; cudaGetSymbolAddress((void**)&ab0, g_ab0);
    char* ab1; cudaGetSymbolAddress((void**)&ab1, g_ab1);

    const int Is[4] = {1024, 2048, 256, 2048};
    const int Os[4] = {2048, 256, 2048, 1024};
    size_t sw_off[4], bw_off[4];
    size_t so = 0, bo = 0;
    for (int li = 0; li < 4; ++li) {
        sw_off[li] = so; bw_off[li] = bo;
        so += (size_t)(Os[li] / 128) * (Is[li] / 64) * 8 * 32768;
        bo += (size_t)(Os[li] / 128) * (Is[li] / 64) * 32768;
    }

    uint32_t fk0[4], fk1[4];
    for (int li = 0; li < 4; ++li)
        threefry2x32_host(0u, 42u, 0u, (uint32_t)li, fk0[li], fk1[li]);

    cudaFuncSetAttribute(kan_mma_kernel,
                         cudaFuncAttributeMaxDynamicSharedMemorySize, SMEM_DYN);

    static cudaStream_t side = [] {
        cudaStream_t s; cudaStreamCreateWithFlags(&s, cudaStreamNonBlocking); return s;
    }();
    static cudaEvent_t evFork = [] {
        cudaEvent_t e; cudaEventCreateWithFlags(&e, cudaEventDisableTiming); return e;
    }();
    static cudaEvent_t evW[4] = {
        [] { cudaEvent_t e; cudaEventCreateWithFlags(&e, cudaEventDisableTiming); return e; }(),
        [] { cudaEvent_t e; cudaEventCreateWithFlags(&e, cudaEventDisableTiming); return e; }(),
        [] { cudaEvent_t e; cudaEventCreateWithFlags(&e, cudaEventDisableTiming); return e; }(),
        [] { cudaEvent_t e; cudaEventCreateWithFlags(&e, cudaEventDisableTiming); return e; }()
    };

    const int mtiles = B / 128;
    dim3 blk(THREADS);

    // ab ping-pong: L0 reads ab0, epilogue writes L1's x-tiles into ab1;
    // L1 reads ab1 (bases filled by pack_bases_pk), writes ab0; etc.
    const char* ab_in[4]  = {ab0, ab1, ab0, ab1};
    char*       ab_out[4] = {ab1, ab0, ab1, nullptr};
    float*      outs[4]   = {nullptr, z, nullptr, xrec};

    auto side_w = [&](int li) {
        size_t tot = (size_t)Is[li] * Os[li] * 4;
        pack_sw_kernel<<<(unsigned)((tot + 255) / 256), 256, 0, side>>>(
            sw[li], swp + sw_off[li], Is[li], Os[li]);
        size_t totb = (size_t)Os[li] * (Is[li] / 2);
        pack_bw_kernel<<<(unsigned)((totb + 255) / 256), 256, 0, side>>>(
            bw[li], bwp + bw_off[li], Is[li], Os[li]);
        cudaEventRecord(evW[li], side);
    };
    auto run_main = [&](int li) {
        dim3 g(Os[li] / 128, mtiles);
        kan_mma_kernel<<<g, blk, SMEM_DYN>>>(
            ab_in[li], swp + sw_off[li], bwp + bw_off[li],
            sb[li], ss[li], sn[li], outs[li], ab_out[li],
            Is[li] / 64, Os[li], fk0[li], fk1[li]);
    };

    cudaEventRecord(evFork, 0);
    cudaStreamWaitEvent(side, evFork, 0);
    for (int li = 0; li < 4; ++li) side_w(li);

    // L0: A-blocks from fp32 input x
    {
        const int nkc0 = Is[0] / 64;
        pack_bases_kernel<<<(unsigned)(mtiles * nkc0 * 8), 256>>>(x, ab0, Is[0], nkc0);
        pack_x_kernel<<<(unsigned)(mtiles * nkc0), 256>>>(x, ab0, Is[0], nkc0);
    }
    cudaStreamWaitEvent(0, evW[0], 0);
    run_main(0);

    // L1..L3: bases from packed x-tiles written by previous epilogue
    for (int li = 1; li < 4; ++li) {
        const int nkc = Is[li] / 64;
        pack_bases_pk_kernel<<<(unsigned)(mtiles * nkc * 8), 256>>>(
            (char*)ab_in[li], nkc);
        cudaStreamWaitEvent(0, evW[li], 0);
        run_main(li);
    }
}

// round 14
// speedup vs baseline: 1.1921x; 1.1921x over previous
#include <cuda_runtime.h>
#include <cuda_bf16.h>
#include <cstdint>
#include <cstddef>

#define THREADS 512

// Scratch activations (fp32)
__device__ float g_h0[8192u * 2048u];
__device__ float g_h2[8192u * 2048u];

// Packed pre-swizzled bf16 hi/lo weights:
// tw blocks (factorized sw): per (layer, ntile, kchunk64, term-tile 0..5): 32KB
// bw blocks: per (layer, ntile, kchunk64): 32KB
__device__ __align__(128) char g_swp[125829120];   // 120MB
__device__ __align__(128) char g_bwp[20971520];    // 20MB
// Packed A-blocks (per layer, reused): per (mtile, kchunk64): 7 blocks of 32KB
// blocks 0..5 = phi tiles (j = i_local*6 + k), block 6 = x tile.
__device__ __align__(128) char g_ab[469762048];

// M[k][g] = g^k/k! * exp(-2e-4*g^2)  (fp64-accurate, rounded to fp32)
__constant__ float TWM[6][8] = {
  {1.0f, 0.99980002f, 0.99920032f, 0.99820162f, 0.99680511f, 0.99501248f, 0.99282590f, 0.99025483f},
  {0.0f, 0.99980002f, 1.99840064f, 2.99460486f, 3.98722045f, 4.97506238f, 5.95695540f, 6.93178379f},
  {0.0f, 0.49990001f, 1.99840064f, 4.49190729f, 7.97444090f, 12.43765595f, 17.87086619f, 24.26124327f},
  {0.0f, 0.16663334f, 1.33226709f, 4.49190729f, 10.63258787f, 20.72942658f, 35.74173238f, 56.60956763f},
  {0.0f, 0.04165833f, 0.66613355f, 3.36893047f, 10.63258787f, 25.91178322f, 53.61259857f, 99.06674336f},
  {0.0f, 0.00833167f, 0.26645342f, 2.02135828f, 8.50607030f, 25.91178322f, 64.33511829f, 138.69344070f}
};

// ---------------- threefry2x32 (JAX-compatible, validated) ----------------
__device__ __forceinline__ uint32_t rotl32d(uint32_t v, int d) {
    return __funnelshift_l(v, v, d);
}
__device__ __forceinline__ void threefry2x32_dev(uint32_t k0, uint32_t k1,
                                                 uint32_t c0, uint32_t c1,
                                                 uint32_t& o0, uint32_t& o1) {
    uint32_t ks2 = k0 ^ k1 ^ 0x1BD11BDAu;
    uint32_t x0 = c0 + k0, x1 = c1 + k1;
#define TF_RND(r) { x0 += x1; x1 = rotl32d(x1, r); x1 ^= x0; }
    TF_RND(13) TF_RND(15) TF_RND(26) TF_RND(6)
    x0 += k1;  x1 += ks2 + 1u;
    TF_RND(17) TF_RND(29) TF_RND(16) TF_RND(24)
    x0 += ks2; x1 += k0 + 2u;
    TF_RND(13) TF_RND(15) TF_RND(26) TF_RND(6)
    x0 += k0;  x1 += k1 + 3u;
    TF_RND(17) TF_RND(29) TF_RND(16) TF_RND(24)
    x0 += k1;  x1 += ks2 + 4u;
    TF_RND(13) TF_RND(15) TF_RND(26) TF_RND(6)
    x0 += ks2; x1 += k0 + 5u;
#undef TF_RND
    o0 = x0; o1 = x1;
}
static inline uint32_t rotl32h(uint32_t v, int d) {
    return (v << d) | (v >> (32 - d));
}
static void threefry2x32_host(uint32_t k0, uint32_t k1, uint32_t c0, uint32_t c1,
                              uint32_t& o0, uint32_t& o1) {
    uint32_t ks2 = k0 ^ k1 ^ 0x1BD11BDAu;
    uint32_t x0 = c0 + k0, x1 = c1 + k1;
#define TF_RND(r) { x0 += x1; x1 = rotl32h(x1, r); x1 ^= x0; }
    TF_RND(13) TF_RND(15) TF_RND(26) TF_RND(6)
    x0 += k1;  x1 += ks2 + 1u;
    TF_RND(17) TF_RND(29) TF_RND(16) TF_RND(24)
    x0 += ks2; x1 += k0 + 2u;
    TF_RND(13) TF_RND(15) TF_RND(26) TF_RND(6)
    x0 += k0;  x1 += k1 + 3u;
    TF_RND(17) TF_RND(29) TF_RND(16) TF_RND(24)
    x0 += k1;  x1 += ks2 + 4u;
    TF_RND(13) TF_RND(15) TF_RND(26) TF_RND(6)
    x0 += ks2; x1 += k0 + 5u;
#undef TF_RND
    o0 = x0; o1 = x1;
}

// ---------------- helpers ----------------
__device__ __forceinline__ uint32_t smem_u32(const void* p) {
    uint32_t a;
    asm("{ .reg .u64 t; cvta.to.shared.u64 t, %1; cvt.u32.u64 %0, t; }"
        : "=r"(a) : "l"(p));
    return a;
}
#define SW128(o) ((o) ^ ((((uint32_t)(o)) >> 3) & 0x70))

#define LDSM4(rv, a) \
    asm volatile("ldmatrix.sync.aligned.m8n8.x4.shared.b16 {%0,%1,%2,%3}, [%4];" \
        : "=r"((rv)[0]), "=r"((rv)[1]), "=r"((rv)[2]), "=r"((rv)[3]) \
        : "r"(a))

#define MMA_BF16(c, a, b0, b1) \
    asm volatile("mma.sync.aligned.m16n8k16.row.col.f32.bf16.bf16.f32 " \
        "{%0,%1,%2,%3}, {%4,%5,%6,%7}, {%8,%9}, {%0,%1,%2,%3};" \
        : "+f"((c)[0]), "+f"((c)[1]), "+f"((c)[2]), "+f"((c)[3]) \
        : "r"((a)[0]), "r"((a)[1]), "r"((a)[2]), "r"((a)[3]), "r"(b0), "r"(b1))

#define CP_ASYNC16(dst, src) \
    asm volatile("cp.async.cg.shared.global [%0], [%1], 16;" \
                 :: "r"((uint32_t)(dst)), "l"(src) : "memory")
#define CP_COMMIT() asm volatile("cp.async.commit_group;" ::: "memory")
#define CP_WAIT0()  asm volatile("cp.async.wait_group 0;" ::: "memory")
#define CP_WAIT1()  asm volatile("cp.async.wait_group 1;" ::: "memory")

__device__ __forceinline__ void bfsplit2(float a, float b, uint32_t& hi2, uint32_t& lo2) {
    asm("cvt.rn.bf16x2.f32 %0, %1, %2;" : "=r"(hi2) : "f"(b), "f"(a));
    __nv_bfloat162 hv = *reinterpret_cast<__nv_bfloat162*>(&hi2);
    float ra = a - __bfloat162float(hv.x);
    float rb = b - __bfloat162float(hv.y);
    asm("cvt.rn.bf16x2.f32 %0, %1, %2;" : "=r"(lo2) : "f"(rb), "f"(ra));
}

// ---------------- pack kernels ----------------
// tw pack: one thread per (i, o); tw[k] = sum_g sw[i,o,g] * TWM[k][g]
__global__ void pack_sw_kernel(const float* __restrict__ sw, char* __restrict__ dst,
                               int I, int O) {
    size_t idx = (size_t)blockIdx.x * blockDim.x + threadIdx.x;
    size_t total = (size_t)I * O;
    if (idx >= total) return;
    int o = (int)(idx % O);
    int i = (int)(idx / O);
    const float4* p = reinterpret_cast<const float4*>(&sw[((size_t)i * O + o) * 8]);
    float4 s0 = p[0], s1 = p[1];
    float s[8] = {s0.x, s0.y, s0.z, s0.w, s1.x, s1.y, s1.z, s1.w};
    float tw[6];
    #pragma unroll
    for (int k = 0; k < 6; ++k) {
        float acc = 0.f;
        #pragma unroll
        for (int g = 0; g < 8; ++g) acc = fmaf(s[g], TWM[k][g], acc);
        tw[k] = acc;
    }
    int tn = o >> 7, n = o & 127, kc = i >> 6, il = i & 63;
    const int nkc = I >> 6;
    size_t blkbase = ((size_t)tn * nkc + kc) * 6;
    #pragma unroll
    for (int pq = 0; pq < 3; ++pq) {
        uint32_t hw, lw;
        bfsplit2(tw[2 * pq], tw[2 * pq + 1], hw, lw);
        int j = il * 6 + 2 * pq;          // even -> pair stays in one tile
        int t = j >> 6, kkk = j & 63;
        size_t blk = (blkbase + t) * 32768;
        uint32_t off = SW128((uint32_t)(n * 128 + kkk * 2));
        *reinterpret_cast<uint32_t*>(dst + blk + off) = hw;
        *reinterpret_cast<uint32_t*>(dst + blk + 16384 + off) = lw;
    }
}

__global__ void pack_bw_kernel(const float* __restrict__ bw, char* __restrict__ dst,
                               int I, int O) {
    size_t idx = (size_t)blockIdx.x * blockDim.x + threadIdx.x;
    size_t total = (size_t)O * (I >> 1);
    if (idx >= total) return;
    int o = (int)(idx % O);
    int kp = (int)(idx / O);
    float b0 = bw[(size_t)(2 * kp) * O + o];
    float b1 = bw[(size_t)(2 * kp + 1) * O + o];
    uint32_t hw, lw;
    bfsplit2(b0, b1, hw, lw);
    int t = o >> 7, n = o & 127;
    int c = (2 * kp) >> 6, klocal = (2 * kp) & 63;
    size_t blk = ((size_t)t * (I >> 6) + c) * 32768;
    uint32_t off = SW128((uint32_t)(n * 128 + klocal * 2));
    *reinterpret_cast<uint32_t*>(dst + blk + off) = hw;
    *reinterpret_cast<uint32_t*>(dst + blk + 16384 + off) = lw;
}

// phi tiles: grid (mtiles*nkc*8); block covers 8 i_locals x 128 m rows
__global__ void pack_phi_kernel(const float* __restrict__ act,
                                char* __restrict__ ab, int I, int nkc) {
    int bid = blockIdx.x;
    int s8 = bid & 7;
    int t2 = bid >> 3;
    int kc = t2 % nkc;
    int mt = t2 / nkc;
    char* base = ab + (size_t)(mt * nkc + kc) * 7 * 32768;
    int tid = threadIdx.x;
    #pragma unroll
    for (int rr = 0; rr < 4; ++rr) {
        int v = rr * 256 + tid;          // 1024 (mloc, il8) tasks
        int mloc = v >> 3, il8 = v & 7;
        int il = s8 * 8 + il8;
        float d = act[(size_t)(mt * 128 + mloc) * I + kc * 64 + il] + 0.044f;
        float E = __expf(-3.125f * d * d);
        float w = 0.05f * d;
        float phi[6];
        phi[0] = E;
        #pragma unroll
        for (int k = 1; k < 6; ++k) phi[k] = phi[k - 1] * w;
        #pragma unroll
        for (int pq = 0; pq < 3; ++pq) {
            uint32_t hw, lw;
            bfsplit2(phi[2 * pq], phi[2 * pq + 1], hw, lw);
            int j = il * 6 + 2 * pq;
            int t = j >> 6, kkk = j & 63;
            uint32_t off = SW128((uint32_t)(mloc * 128 + kkk * 2));
            *reinterpret_cast<uint32_t*>(base + t * 32768 + off) = hw;
            *reinterpret_cast<uint32_t*>(base + t * 32768 + 16384 + off) = lw;
        }
    }
}

// x tiles (block 6)
__global__ void pack_x_kernel(const float* __restrict__ act,
                              char* __restrict__ ab, int I, int nkc) {
    int bid = blockIdx.x;
    int kc = bid % nkc;
    int mt = bid / nkc;
    char* blk = ab + ((size_t)(mt * nkc + kc) * 7 + 6) * 32768;
    int tid = threadIdx.x;
    #pragma unroll
    for (int rr = 0; rr < 8; ++rr) {
        int v = rr * 256 + tid;
        int mloc = v >> 4, c4 = v & 15;
        float4 xv = *reinterpret_cast<const float4*>(
            &act[(size_t)(mt * 128 + mloc) * I + kc * 64 + c4 * 4]);
        uint32_t h0w, l0w, h1w, l1w;
        bfsplit2(xv.x, xv.y, h0w, l0w);
        bfsplit2(xv.z, xv.w, h1w, l1w);
        uint32_t off = SW128((uint32_t)(mloc * 128 + c4 * 8));
        *reinterpret_cast<uint2*>(blk + off) = make_uint2(h0w, h1w);
        *reinterpret_cast<uint2*>(blk + 16384 + off) = make_uint2(l0w, l1w);
    }
}

// ---------------- SMEM: 3-stage ring, 64KB per stage ----------------
static constexpr int STAGE_STRIDE = 65536;
static constexpr int NSTAGE = 3;
static constexpr int SMEM_SZ = NSTAGE * STAGE_STRIDE;   // 192KB
static constexpr int SMEM_DYN = SMEM_SZ + 1024;

// ---------------- main kernel: R11 mainloop, 7 stages per kchunk --------------
__global__ __launch_bounds__(THREADS, 1)
void kan_mma_kernel(const char* __restrict__ ab,
                    const char* __restrict__ swp,
                    const char* __restrict__ bwp,
                    const float* __restrict__ sbp,
                    const float* __restrict__ ssp,
                    const float* __restrict__ snp,
                    float* __restrict__ outp,
                    int nkc, int O,
                    uint32_t nk0, uint32_t nk1) {
    extern __shared__ char raw[];
    const uint32_t rawu = smem_u32(raw);
    const uint32_t sbase = (rawu + 1023u) & ~1023u;

    const int tid = threadIdx.x;
    const int wid = tid >> 5;
    const int lid = tid & 31;
    const int wm  = wid >> 2;
    const int wn  = wid & 3;
    const int m0  = blockIdx.y * 128;
    const int n0  = blockIdx.x * 128;   // n fastest
    const int mt  = blockIdx.y;

    const int q = lid >> 3, r = lid & 7;
    const int rowA_l = r + (q & 1) * 8;
    const int kselA  = (q >> 1) * 16;
    const int rowB_l = r + (q >> 1) * 8;
    const int kselB  = (q & 1) * 16;

    float accS[2][4][4];
    float accB[2][4][4];
    #pragma unroll
    for (int a = 0; a < 2; ++a)
        #pragma unroll
        for (int b = 0; b < 4; ++b)
            #pragma unroll
            for (int e = 0; e < 4; ++e) { accS[a][b][e] = 0.f; accB[a][b][e] = 0.f; }

    const size_t a_tile = (size_t)mt * nkc;
    const size_t b_tile = (size_t)(n0 >> 7) * nkc;
    const int total = nkc * 7;

    auto issue_stage = [&](int s) {
        int kc = s / 7, sub = s - kc * 7;
        uint32_t dst = sbase + (s % NSTAGE) * STAGE_STRIDE;
        const char* asrc = ab + ((a_tile + kc) * 7 + sub) * 32768;
        const char* bsrc = (sub < 6)
            ? swp + ((b_tile + kc) * 6 + sub) * 32768
            : bwp + (b_tile + kc) * 32768;
        #pragma unroll
        for (int rr = 0; rr < 4; ++rr) {
            uint32_t off = (uint32_t)(rr * THREADS + tid) * 16;
            CP_ASYNC16(dst + off, asrc + off);
        }
        #pragma unroll
        for (int rr = 0; rr < 4; ++rr) {
            uint32_t off = (uint32_t)(rr * THREADS + tid) * 16;
            CP_ASYNC16(dst + 32768 + off, bsrc + off);
        }
        CP_COMMIT();
    };

    auto do_mma = [&](int buf, float (&acc)[2][4][4]) {
        const uint32_t Ah = sbase + buf * STAGE_STRIDE;
        const uint32_t Al = Ah + 16384;
        const uint32_t Bh = Ah + 32768;
        const uint32_t Bl = Ah + 49152;
        #pragma unroll
        for (int k16 = 0; k16 < 4; ++k16) {
            const int kbyt = k16 * 32;
            uint32_t ah[2][4], al[2][4];
            #pragma unroll
            for (int mf = 0; mf < 2; ++mf) {
                int m = wm * 32 + mf * 16 + rowA_l;
                uint32_t off = (uint32_t)(m * 128)
                             + (((uint32_t)(kbyt + kselA)) ^ ((m * 16) & 0x70));
                LDSM4(ah[mf], Ah + off);
                LDSM4(al[mf], Al + off);
            }
            uint32_t bh[2][4], bl[2][4];
            #pragma unroll
            for (int nb = 0; nb < 2; ++nb) {
                int n = wn * 32 + nb * 16 + rowB_l;
                uint32_t off = (uint32_t)(n * 128)
                             + (((uint32_t)(kbyt + kselB)) ^ ((n * 16) & 0x70));
                LDSM4(bh[nb], Bh + off);
                LDSM4(bl[nb], Bl + off);
            }
            #pragma unroll
            for (int mf = 0; mf < 2; ++mf)
                #pragma unroll
                for (int nf = 0; nf < 4; ++nf) {
                    const int nb = nf >> 1, ri = (nf & 1) * 2;
                    MMA_BF16(acc[mf][nf], ah[mf], bh[nb][ri], bh[nb][ri + 1]);
                    MMA_BF16(acc[mf][nf], ah[mf], bl[nb][ri], bl[nb][ri + 1]);
                    MMA_BF16(acc[mf][nf], al[mf], bh[nb][ri], bh[nb][ri + 1]);
                }
        }
    };

    issue_stage(0);
    issue_stage(1);
    for (int s = 0; s < total; ++s) {
        if (s < total - 1) { CP_WAIT1(); } else { CP_WAIT0(); }
        __syncthreads();
        int sub = s % 7;
        if (sub == 6) do_mma(s % NSTAGE, accB);
        else          do_mma(s % NSTAGE, accS);
        if (s + 2 < total) issue_stage(s + 2);
    }

    // ---------------- epilogue ----------------
    const float snv = *snp;
    const int rq = lid >> 2, cq = (lid & 3) * 2;
    #pragma unroll
    for (int mf = 0; mf < 2; ++mf) {
        #pragma unroll
        for (int nf = 0; nf < 4; ++nf) {
            #pragma unroll
            for (int half = 0; half < 2; ++half) {
                int b = m0 + wm * 32 + mf * 16 + rq + half * 8;
                int obase = n0 + wn * 32 + nf * 8 + cq;
                float2 res;
                #pragma unroll
                for (int e = 0; e < 2; ++e) {
                    int o = obase + e;
                    float sv = accS[mf][nf][half * 2 + e];
                    float bv = accB[mf][nf][half * 2 + e];
                    float sg = 1.0f / (1.0f + __expf(-bv));
                    uint32_t li = (uint32_t)b * (uint32_t)O + (uint32_t)o;
                    uint32_t r0, r1;
                    threefry2x32_dev(nk0, nk1, 0u, li, r0, r1);
                    uint32_t bits = r0 ^ r1;
                    float f = __uint_as_float((bits >> 9) | 0x3f800000u) - 1.0f;
                    float uu = fmaxf(-0.99999994f, fmaf(f, 2.0f, -0.99999994f));
                    float nz = 1.41421356f * erfinvf(uu);
                    float val = bv * sg * sbp[o] + sv * ssp[o] + nz * snv;
                    if (e == 0) res.x = val; else res.y = val;
                }
                *reinterpret_cast<float2*>(&outp[(size_t)b * O + obase]) = res;
            }
        }
    }
}

// ---------------- launch (R11 structure) ----------------
extern "C" void kernel_launch(void* const* d_in, const int* in_sizes, int n_in,
                              void* d_out, int out_size) {
    const float* x = (const float*)d_in[0];
    const float* sw[4]; const float* bw[4]; const float* sb[4];
    const float* ss[4]; const float* sn[4];
    for (int li = 0; li < 4; ++li) {
        sw[li] = (const float*)d_in[1 + 5 * li + 0];
        bw[li] = (const float*)d_in[1 + 5 * li + 1];
        sb[li] = (const float*)d_in[1 + 5 * li + 2];
        ss[li] = (const float*)d_in[1 + 5 * li + 3];
        sn[li] = (const float*)d_in[1 + 5 * li + 4];
    }
    const int B = in_sizes[0] / 1024;   // 8192
    float* out  = (float*)d_out;
    float* xrec = out;
    float* z    = out + (size_t)B * 1024;

    float* h0; cudaGetSymbolAddress((void**)&h0, g_h0);
    float* h2; cudaGetSymbolAddress((void**)&h2, g_h2);
    char* swp; cudaGetSymbolAddress((void**)&swp, g_swp);
    char* bwp; cudaGetSymbolAddress((void**)&bwp, g_bwp);
    char* ab;  cudaGetSymbolAddress((void**)&ab, g_ab);

    const int Is[4] = {1024, 2048, 256, 2048};
    const int Os[4] = {2048, 256, 2048, 1024};
    size_t sw_off[4], bw_off[4];
    size_t so = 0, bo = 0;
    for (int li = 0; li < 4; ++li) {
        sw_off[li] = so; bw_off[li] = bo;
        so += (size_t)(Os[li] / 128) * (Is[li] / 64) * 6 * 32768;
        bo += (size_t)(Os[li] / 128) * (Is[li] / 64) * 32768;
    }

    uint32_t fk0[4], fk1[4];
    for (int li = 0; li < 4; ++li)
        threefry2x32_host(0u, 42u, 0u, (uint32_t)li, fk0[li], fk1[li]);

    cudaFuncSetAttribute(kan_mma_kernel,
                         cudaFuncAttributeMaxDynamicSharedMemorySize, SMEM_DYN);

    static cudaStream_t side = [] {
        cudaStream_t s; cudaStreamCreateWithFlags(&s, cudaStreamNonBlocking); return s;
    }();
    static cudaEvent_t evFork = [] {
        cudaEvent_t e; cudaEventCreateWithFlags(&e, cudaEventDisableTiming); return e;
    }();
    static cudaEvent_t evW[4] = {
        [] { cudaEvent_t e; cudaEventCreateWithFlags(&e, cudaEventDisableTiming); return e; }(),
        [] { cudaEvent_t e; cudaEventCreateWithFlags(&e, cudaEventDisableTiming); return e; }(),
        [] { cudaEvent_t e; cudaEventCreateWithFlags(&e, cudaEventDisableTiming); return e; }(),
        [] { cudaEvent_t e; cudaEventCreateWithFlags(&e, cudaEventDisableTiming); return e; }()
    };

    const int mtiles = B / 128;
    dim3 blk(THREADS);
    const float* ins[4]  = {x, h0, z, h2};
    float* outs[4]       = {h0, z, h2, xrec};

    auto side_w = [&](int li) {
        size_t tot = (size_t)Is[li] * Os[li];
        pack_sw_kernel<<<(unsigned)((tot + 255) / 256), 256, 0, side>>>(
            sw[li], swp + sw_off[li], Is[li], Os[li]);
        size_t totb = (size_t)Os[li] * (Is[li] / 2);
        pack_bw_kernel<<<(unsigned)((totb + 255) / 256), 256, 0, side>>>(
            bw[li], bwp + bw_off[li], Is[li], Os[li]);
        cudaEventRecord(evW[li], side);
    };
    auto pack_a_main = [&](int li) {
        const int nkc = Is[li] / 64;
        pack_phi_kernel<<<(unsigned)(mtiles * nkc * 8), 256>>>(ins[li], ab, Is[li], nkc);
        pack_x_kernel<<<(unsigned)(mtiles * nkc), 256>>>(ins[li], ab, Is[li], nkc);
    };
    auto run_main = [&](int li) {
        dim3 g(Os[li] / 128, mtiles);
        kan_mma_kernel<<<g, blk, SMEM_DYN>>>(
            ab, swp + sw_off[li], bwp + bw_off[li],
            sb[li], ss[li], sn[li], outs[li],
            Is[li] / 64, Os[li], fk0[li], fk1[li]);
    };

    cudaEventRecord(evFork, 0);
    cudaStreamWaitEvent(side, evFork, 0);
    for (int li = 0; li < 4; ++li) side_w(li);

    for (int li = 0; li < 4; ++li) {
        pack_a_main(li);
        cudaStreamWaitEvent(0, evW[li], 0);
        run_main(li);
    }
}

// round 15
// speedup vs baseline: 1.4472x; 1.2140x over previous
#include <cuda_runtime.h>
#include <cuda_bf16.h>
#include <cstdint>
#include <cstddef>

#define THREADS 512

// Scratch activations (fp32)
__device__ float g_h0[8192u * 2048u];
__device__ float g_h2[8192u * 2048u];

// Packed pre-swizzled bf16 hi/lo weights:
// tw blocks (factorized sw): per (layer, ntile, kchunk64, term 0..4): 32KB
//   term-major k-dim: j = k*64 + il
// bw blocks: per (layer, ntile, kchunk64): 32KB
__device__ __align__(128) char g_swp[104857600];   // 100MB
__device__ __align__(128) char g_bwp[20971520];    // 20MB
// Packed A-blocks: per (mtile, kchunk64): 6 blocks of 32KB
// blocks 0..4 = phi term tiles (j = k*64 + il), block 5 = x tile.
__device__ __align__(128) char g_ab[402653184];    // 384MB

// M[k][g] = g^k/k! * exp(-2e-4*g^2), k = 0..4
__constant__ float TWM[5][8] = {
  {1.0f, 0.99980002f, 0.99920032f, 0.99820162f, 0.99680511f, 0.99501248f, 0.99282590f, 0.99025483f},
  {0.0f, 0.99980002f, 1.99840064f, 2.99460486f, 3.98722045f, 4.97506238f, 5.95695540f, 6.93178379f},
  {0.0f, 0.49990001f, 1.99840064f, 4.49190729f, 7.97444090f, 12.43765595f, 17.87086619f, 24.26124327f},
  {0.0f, 0.16663334f, 1.33226709f, 4.49190729f, 10.63258787f, 20.72942658f, 35.74173238f, 56.60956763f},
  {0.0f, 0.04165833f, 0.66613355f, 3.36893047f, 10.63258787f, 25.91178322f, 53.61259857f, 99.06674336f}
};

// ---------------- threefry2x32 (JAX-compatible, validated) ----------------
__device__ __forceinline__ uint32_t rotl32d(uint32_t v, int d) {
    return __funnelshift_l(v, v, d);
}
__device__ __forceinline__ void threefry2x32_dev(uint32_t k0, uint32_t k1,
                                                 uint32_t c0, uint32_t c1,
                                                 uint32_t& o0, uint32_t& o1) {
    uint32_t ks2 = k0 ^ k1 ^ 0x1BD11BDAu;
    uint32_t x0 = c0 + k0, x1 = c1 + k1;
#define TF_RND(r) { x0 += x1; x1 = rotl32d(x1, r); x1 ^= x0; }
    TF_RND(13) TF_RND(15) TF_RND(26) TF_RND(6)
    x0 += k1;  x1 += ks2 + 1u;
    TF_RND(17) TF_RND(29) TF_RND(16) TF_RND(24)
    x0 += ks2; x1 += k0 + 2u;
    TF_RND(13) TF_RND(15) TF_RND(26) TF_RND(6)
    x0 += k0;  x1 += k1 + 3u;
    TF_RND(17) TF_RND(29) TF_RND(16) TF_RND(24)
    x0 += k1;  x1 += ks2 + 4u;
    TF_RND(13) TF_RND(15) TF_RND(26) TF_RND(6)
    x0 += ks2; x1 += k0 + 5u;
#undef TF_RND
    o0 = x0; o1 = x1;
}
static inline uint32_t rotl32h(uint32_t v, int d) {
    return (v << d) | (v >> (32 - d));
}
static void threefry2x32_host(uint32_t k0, uint32_t k1, uint32_t c0, uint32_t c1,
                              uint32_t& o0, uint32_t& o1) {
    uint32_t ks2 = k0 ^ k1 ^ 0x1BD11BDAu;
    uint32_t x0 = c0 + k0, x1 = c1 + k1;
#define TF_RND(r) { x0 += x1; x1 = rotl32h(x1, r); x1 ^= x0; }
    TF_RND(13) TF_RND(15) TF_RND(26) TF_RND(6)
    x0 += k1;  x1 += ks2 + 1u;
    TF_RND(17) TF_RND(29) TF_RND(16) TF_RND(24)
    x0 += ks2; x1 += k0 + 2u;
    TF_RND(13) TF_RND(15) TF_RND(26) TF_RND(6)
    x0 += k0;  x1 += k1 + 3u;
    TF_RND(17) TF_RND(29) TF_RND(16) TF_RND(24)
    x0 += k1;  x1 += ks2 + 4u;
    TF_RND(13) TF_RND(15) TF_RND(26) TF_RND(6)
    x0 += ks2; x1 += k0 + 5u;
#undef TF_RND
    o0 = x0; o1 = x1;
}

// ---------------- helpers ----------------
__device__ __forceinline__ uint32_t smem_u32(const void* p) {
    uint32_t a;
    asm("{ .reg .u64 t; cvta.to.shared.u64 t, %1; cvt.u32.u64 %0, t; }"
        : "=r"(a) : "l"(p));
    return a;
}
#define SW128(o) ((o) ^ ((((uint32_t)(o)) >> 3) & 0x70))

#define LDSM4(rv, a) \
    asm volatile("ldmatrix.sync.aligned.m8n8.x4.shared.b16 {%0,%1,%2,%3}, [%4];" \
        : "=r"((rv)[0]), "=r"((rv)[1]), "=r"((rv)[2]), "=r"((rv)[3]) \
        : "r"(a))

#define MMA_BF16(c, a, b0, b1) \
    asm volatile("mma.sync.aligned.m16n8k16.row.col.f32.bf16.bf16.f32 " \
        "{%0,%1,%2,%3}, {%4,%5,%6,%7}, {%8,%9}, {%0,%1,%2,%3};" \
        : "+f"((c)[0]), "+f"((c)[1]), "+f"((c)[2]), "+f"((c)[3]) \
        : "r"((a)[0]), "r"((a)[1]), "r"((a)[2]), "r"((a)[3]), "r"(b0), "r"(b1))

#define CP_ASYNC16(dst, src) \
    asm volatile("cp.async.cg.shared.global [%0], [%1], 16;" \
                 :: "r"((uint32_t)(dst)), "l"(src) : "memory")
#define CP_COMMIT() asm volatile("cp.async.commit_group;" ::: "memory")
#define CP_WAIT0()  asm volatile("cp.async.wait_group 0;" ::: "memory")
#define CP_WAIT1()  asm volatile("cp.async.wait_group 1;" ::: "memory")

__device__ __forceinline__ void bfsplit2(float a, float b, uint32_t& hi2, uint32_t& lo2) {
    asm("cvt.rn.bf16x2.f32 %0, %1, %2;" : "=r"(hi2) : "f"(b), "f"(a));
    __nv_bfloat162 hv = *reinterpret_cast<__nv_bfloat162*>(&hi2);
    float ra = a - __bfloat162float(hv.x);
    float rb = b - __bfloat162float(hv.y);
    asm("cvt.rn.bf16x2.f32 %0, %1, %2;" : "=r"(lo2) : "f"(rb), "f"(ra));
}

// ---------------- pack kernels ----------------
// tw pack: one thread per (i-pair, o); term-major j = k*64 + il
__global__ void pack_sw_kernel(const float* __restrict__ sw, char* __restrict__ dst,
                               int I, int O) {
    size_t idx = (size_t)blockIdx.x * blockDim.x + threadIdx.x;
    size_t total = (size_t)(I >> 1) * O;
    if (idx >= total) return;
    int o  = (int)(idx % O);
    int ip = (int)(idx / O);
    int i0 = 2 * ip;
    float tw[2][5];
    #pragma unroll
    for (int e = 0; e < 2; ++e) {
        const float4* p = reinterpret_cast<const float4*>(
            &sw[((size_t)(i0 + e) * O + o) * 8]);
        float4 s0 = p[0], s1 = p[1];
        float s[8] = {s0.x, s0.y, s0.z, s0.w, s1.x, s1.y, s1.z, s1.w};
        #pragma unroll
        for (int k = 0; k < 5; ++k) {
            float acc = 0.f;
            #pragma unroll
            for (int g = 0; g < 8; ++g) acc = fmaf(s[g], TWM[k][g], acc);
            tw[e][k] = acc;
        }
    }
    int tn = o >> 7, n = o & 127, kc = i0 >> 6, il0 = i0 & 63;
    const int nkc = I >> 6;
    size_t blkbase = ((size_t)tn * nkc + kc) * 5;
    #pragma unroll
    for (int k = 0; k < 5; ++k) {
        uint32_t hw, lw;
        bfsplit2(tw[0][k], tw[1][k], hw, lw);
        size_t blk = (blkbase + k) * 32768;
        uint32_t off = SW128((uint32_t)(n * 128 + il0 * 2));
        *reinterpret_cast<uint32_t*>(dst + blk + off) = hw;
        *reinterpret_cast<uint32_t*>(dst + blk + 16384 + off) = lw;
    }
}

__global__ void pack_bw_kernel(const float* __restrict__ bw, char* __restrict__ dst,
                               int I, int O) {
    size_t idx = (size_t)blockIdx.x * blockDim.x + threadIdx.x;
    size_t total = (size_t)O * (I >> 1);
    if (idx >= total) return;
    int o = (int)(idx % O);
    int kp = (int)(idx / O);
    float b0 = bw[(size_t)(2 * kp) * O + o];
    float b1 = bw[(size_t)(2 * kp + 1) * O + o];
    uint32_t hw, lw;
    bfsplit2(b0, b1, hw, lw);
    int t = o >> 7, n = o & 127;
    int c = (2 * kp) >> 6, klocal = (2 * kp) & 63;
    size_t blk = ((size_t)t * (I >> 6) + c) * 32768;
    uint32_t off = SW128((uint32_t)(n * 128 + klocal * 2));
    *reinterpret_cast<uint32_t*>(dst + blk + off) = hw;
    *reinterpret_cast<uint32_t*>(dst + blk + 16384 + off) = lw;
}

// phi tiles, term-major: grid (mtiles*nkc*4); thread handles (mloc, il-pair)
__global__ void pack_phi_kernel(const float* __restrict__ act,
                                char* __restrict__ ab, int I, int nkc) {
    int bid = blockIdx.x;
    int s4 = bid & 3;
    int t2 = bid >> 2;
    int kc = t2 % nkc;
    int mt = t2 / nkc;
    char* base = ab + (size_t)(mt * nkc + kc) * 6 * 32768;
    int tid = threadIdx.x;
    #pragma unroll
    for (int rr = 0; rr < 4; ++rr) {
        int v = rr * 256 + tid;          // 1024 (mloc, p) tasks
        int mloc = v >> 3, p = v & 7;
        int ilp = s4 * 8 + p;            // pair index 0..31
        int il0 = ilp * 2;
        float2 xv = *reinterpret_cast<const float2*>(
            &act[(size_t)(mt * 128 + mloc) * I + kc * 64 + il0]);
        float phi[2][5];
        #pragma unroll
        for (int e = 0; e < 2; ++e) {
            float d = (e ? xv.y : xv.x) + 0.044f;
            float E = __expf(-3.125f * d * d);
            float w = 0.05f * d;
            phi[e][0] = E;
            #pragma unroll
            for (int k = 1; k < 5; ++k) phi[e][k] = phi[e][k - 1] * w;
        }
        uint32_t off = SW128((uint32_t)(mloc * 128 + ilp * 4));
        #pragma unroll
        for (int k = 0; k < 5; ++k) {
            uint32_t hw, lw;
            bfsplit2(phi[0][k], phi[1][k], hw, lw);
            *reinterpret_cast<uint32_t*>(base + k * 32768 + off) = hw;
            *reinterpret_cast<uint32_t*>(base + k * 32768 + 16384 + off) = lw;
        }
    }
}

// x tiles (block 5)
__global__ void pack_x_kernel(const float* __restrict__ act,
                              char* __restrict__ ab, int I, int nkc) {
    int bid = blockIdx.x;
    int kc = bid % nkc;
    int mt = bid / nkc;
    char* blk = ab + ((size_t)(mt * nkc + kc) * 6 + 5) * 32768;
    int tid = threadIdx.x;
    #pragma unroll
    for (int rr = 0; rr < 8; ++rr) {
        int v = rr * 256 + tid;
        int mloc = v >> 4, c4 = v & 15;
        float4 xv = *reinterpret_cast<const float4*>(
            &act[(size_t)(mt * 128 + mloc) * I + kc * 64 + c4 * 4]);
        uint32_t h0w, l0w, h1w, l1w;
        bfsplit2(xv.x, xv.y, h0w, l0w);
        bfsplit2(xv.z, xv.w, h1w, l1w);
        uint32_t off = SW128((uint32_t)(mloc * 128 + c4 * 8));
        *reinterpret_cast<uint2*>(blk + off) = make_uint2(h0w, h1w);
        *reinterpret_cast<uint2*>(blk + 16384 + off) = make_uint2(l0w, l1w);
    }
}

// ---------------- SMEM: 3-stage ring, 64KB per stage ----------------
static constexpr int STAGE_STRIDE = 65536;
static constexpr int NSTAGE = 3;
static constexpr int SMEM_SZ = NSTAGE * STAGE_STRIDE;   // 192KB
static constexpr int SMEM_DYN = SMEM_SZ + 1024;

// ---------------- main kernel: R11 mainloop, 6 stages per kchunk --------------
__global__ __launch_bounds__(THREADS, 1)
void kan_mma_kernel(const char* __restrict__ ab,
                    const char* __restrict__ swp,
                    const char* __restrict__ bwp,
                    const float* __restrict__ sbp,
                    const float* __restrict__ ssp,
                    const float* __restrict__ snp,
                    float* __restrict__ outp,
                    int nkc, int O,
                    uint32_t nk0, uint32_t nk1) {
    extern __shared__ char raw[];
    const uint32_t rawu = smem_u32(raw);
    const uint32_t sbase = (rawu + 1023u) & ~1023u;

    const int tid = threadIdx.x;
    const int wid = tid >> 5;
    const int lid = tid & 31;
    const int wm  = wid >> 2;
    const int wn  = wid & 3;
    const int m0  = blockIdx.y * 128;
    const int n0  = blockIdx.x * 128;   // n fastest
    const int mt  = blockIdx.y;

    const int q = lid >> 3, r = lid & 7;
    const int rowA_l = r + (q & 1) * 8;
    const int kselA  = (q >> 1) * 16;
    const int rowB_l = r + (q >> 1) * 8;
    const int kselB  = (q & 1) * 16;

    float accS[2][4][4];
    float accB[2][4][4];
    #pragma unroll
    for (int a = 0; a < 2; ++a)
        #pragma unroll
        for (int b = 0; b < 4; ++b)
            #pragma unroll
            for (int e = 0; e < 4; ++e) { accS[a][b][e] = 0.f; accB[a][b][e] = 0.f; }

    const size_t a_tile = (size_t)mt * nkc;
    const size_t b_tile = (size_t)(n0 >> 7) * nkc;
    const int total = nkc * 6;

    auto issue_stage = [&](int s) {
        int kc = s / 6, sub = s - kc * 6;
        uint32_t dst = sbase + (s % NSTAGE) * STAGE_STRIDE;
        const char* asrc = ab + ((a_tile + kc) * 6 + sub) * 32768;
        const char* bsrc = (sub < 5)
            ? swp + ((b_tile + kc) * 5 + sub) * 32768
            : bwp + (b_tile + kc) * 32768;
        #pragma unroll
        for (int rr = 0; rr < 4; ++rr) {
            uint32_t off = (uint32_t)(rr * THREADS + tid) * 16;
            CP_ASYNC16(dst + off, asrc + off);
        }
        #pragma unroll
        for (int rr = 0; rr < 4; ++rr) {
            uint32_t off = (uint32_t)(rr * THREADS + tid) * 16;
            CP_ASYNC16(dst + 32768 + off, bsrc + off);
        }
        CP_COMMIT();
    };

    auto do_mma = [&](int buf, float (&acc)[2][4][4]) {
        const uint32_t Ah = sbase + buf * STAGE_STRIDE;
        const uint32_t Al = Ah + 16384;
        const uint32_t Bh = Ah + 32768;
        const uint32_t Bl = Ah + 49152;
        #pragma unroll
        for (int k16 = 0; k16 < 4; ++k16) {
            const int kbyt = k16 * 32;
            uint32_t ah[2][4], al[2][4];
            #pragma unroll
            for (int mf = 0; mf < 2; ++mf) {
                int m = wm * 32 + mf * 16 + rowA_l;
                uint32_t off = (uint32_t)(m * 128)
                             + (((uint32_t)(kbyt + kselA)) ^ ((m * 16) & 0x70));
                LDSM4(ah[mf], Ah + off);
                LDSM4(al[mf], Al + off);
            }
            uint32_t bh[2][4], bl[2][4];
            #pragma unroll
            for (int nb = 0; nb < 2; ++nb) {
                int n = wn * 32 + nb * 16 + rowB_l;
                uint32_t off = (uint32_t)(n * 128)
                             + (((uint32_t)(kbyt + kselB)) ^ ((n * 16) & 0x70));
                LDSM4(bh[nb], Bh + off);
                LDSM4(bl[nb], Bl + off);
            }
            #pragma unroll
            for (int mf = 0; mf < 2; ++mf)
                #pragma unroll
                for (int nf = 0; nf < 4; ++nf) {
                    const int nb = nf >> 1, ri = (nf & 1) * 2;
                    MMA_BF16(acc[mf][nf], ah[mf], bh[nb][ri], bh[nb][ri + 1]);
                    MMA_BF16(acc[mf][nf], ah[mf], bl[nb][ri], bl[nb][ri + 1]);
                    MMA_BF16(acc[mf][nf], al[mf], bh[nb][ri], bh[nb][ri + 1]);
                }
        }
    };

    issue_stage(0);
    issue_stage(1);
    for (int s = 0; s < total; ++s) {
        if (s < total - 1) { CP_WAIT1(); } else { CP_WAIT0(); }
        __syncthreads();
        int sub = s % 6;
        if (sub == 5) do_mma(s % NSTAGE, accB);
        else          do_mma(s % NSTAGE, accS);
        if (s + 2 < total) issue_stage(s + 2);
    }

    // ---------------- epilogue ----------------
    const float snv = *snp;
    const int rq = lid >> 2, cq = (lid & 3) * 2;
    #pragma unroll
    for (int mf = 0; mf < 2; ++mf) {
        #pragma unroll
        for (int nf = 0; nf < 4; ++nf) {
            #pragma unroll
            for (int half = 0; half < 2; ++half) {
                int b = m0 + wm * 32 + mf * 16 + rq + half * 8;
                int obase = n0 + wn * 32 + nf * 8 + cq;
                float2 res;
                #pragma unroll
                for (int e = 0; e < 2; ++e) {
                    int o = obase + e;
                    float sv = accS[mf][nf][half * 2 + e];
                    float bv = accB[mf][nf][half * 2 + e];
                    float sg = 1.0f / (1.0f + __expf(-bv));
                    uint32_t li = (uint32_t)b * (uint32_t)O + (uint32_t)o;
                    uint32_t r0, r1;
                    threefry2x32_dev(nk0, nk1, 0u, li, r0, r1);
                    uint32_t bits = r0 ^ r1;
                    float f = __uint_as_float((bits >> 9) | 0x3f800000u) - 1.0f;
                    float uu = fmaxf(-0.99999994f, fmaf(f, 2.0f, -0.99999994f));
                    float nz = 1.41421356f * erfinvf(uu);
                    float val = bv * sg * sbp[o] + sv * ssp[o] + nz * snv;
                    if (e == 0) res.x = val; else res.y = val;
                }
                *reinterpret_cast<float2*>(&outp[(size_t)b * O + obase]) = res;
            }
        }
    }
}

// ---------------- launch (R11/R14 structure) ----------------
extern "C" void kernel_launch(void* const* d_in, const int* in_sizes, int n_in,
                              void* d_out, int out_size) {
    const float* x = (const float*)d_in[0];
    const float* sw[4]; const float* bw[4]; const float* sb[4];
    const float* ss[4]; const float* sn[4];
    for (int li = 0; li < 4; ++li) {
        sw[li] = (const float*)d_in[1 + 5 * li + 0];
        bw[li] = (const float*)d_in[1 + 5 * li + 1];
        sb[li] = (const float*)d_in[1 + 5 * li + 2];
        ss[li] = (const float*)d_in[1 + 5 * li + 3];
        sn[li] = (const float*)d_in[1 + 5 * li + 4];
    }
    const int B = in_sizes[0] / 1024;   // 8192
    float* out  = (float*)d_out;
    float* xrec = out;
    float* z    = out + (size_t)B * 1024;

    float* h0; cudaGetSymbolAddress((void**)&h0, g_h0);
    float* h2; cudaGetSymbolAddress((void**)&h2, g_h2);
    char* swp; cudaGetSymbolAddress((void**)&swp, g_swp);
    char* bwp; cudaGetSymbolAddress((void**)&bwp, g_bwp);
    char* ab;  cudaGetSymbolAddress((void**)&ab, g_ab);

    const int Is[4] = {1024, 2048, 256, 2048};
    const int Os[4] = {2048, 256, 2048, 1024};
    size_t sw_off[4], bw_off[4];
    size_t so = 0, bo = 0;
    for (int li = 0; li < 4; ++li) {
        sw_off[li] = so; bw_off[li] = bo;
        so += (size_t)(Os[li] / 128) * (Is[li] / 64) * 5 * 32768;
        bo += (size_t)(Os[li] / 128) * (Is[li] / 64) * 32768;
    }

    uint32_t fk0[4], fk1[4];
    for (int li = 0; li < 4; ++li)
        threefry2x32_host(0u, 42u, 0u, (uint32_t)li, fk0[li], fk1[li]);

    cudaFuncSetAttribute(kan_mma_kernel,
                         cudaFuncAttributeMaxDynamicSharedMemorySize, SMEM_DYN);

    static cudaStream_t side = [] {
        cudaStream_t s; cudaStreamCreateWithFlags(&s, cudaStreamNonBlocking); return s;
    }();
    static cudaEvent_t evFork = [] {
        cudaEvent_t e; cudaEventCreateWithFlags(&e, cudaEventDisableTiming); return e;
    }();
    static cudaEvent_t evW[4] = {
        [] { cudaEvent_t e; cudaEventCreateWithFlags(&e, cudaEventDisableTiming); return e; }(),
        [] { cudaEvent_t e; cudaEventCreateWithFlags(&e, cudaEventDisableTiming); return e; }(),
        [] { cudaEvent_t e; cudaEventCreateWithFlags(&e, cudaEventDisableTiming); return e; }(),
        [] { cudaEvent_t e; cudaEventCreateWithFlags(&e, cudaEventDisableTiming); return e; }()
    };

    const int mtiles = B / 128;
    dim3 blk(THREADS);
    const float* ins[4]  = {x, h0, z, h2};
    float* outs[4]       = {h0, z, h2, xrec};

    auto side_w = [&](int li) {
        size_t tot = (size_t)(Is[li] / 2) * Os[li];
        pack_sw_kernel<<<(unsigned)((tot + 255) / 256), 256, 0, side>>>(
            sw[li], swp + sw_off[li], Is[li], Os[li]);
        size_t totb = (size_t)Os[li] * (Is[li] / 2);
        pack_bw_kernel<<<(unsigned)((totb + 255) / 256), 256, 0, side>>>(
            bw[li], bwp + bw_off[li], Is[li], Os[li]);
        cudaEventRecord(evW[li], side);
    };
    auto pack_a_main = [&](int li) {
        const int nkc = Is[li] / 64;
        pack_phi_kernel<<<(unsigned)(mtiles * nkc * 4), 256>>>(ins[li], ab, Is[li], nkc);
        pack_x_kernel<<<(unsigned)(mtiles * nkc), 256>>>(ins[li], ab, Is[li], nkc);
    };
    auto run_main = [&](int li) {
        dim3 g(Os[li] / 128, mtiles);
        kan_mma_kernel<<<g, blk, SMEM_DYN>>>(
            ab, swp + sw_off[li], bwp + bw_off[li],
            sb[li], ss[li], sn[li], outs[li],
            Is[li] / 64, Os[li], fk0[li], fk1[li]);
    };

    cudaEventRecord(evFork, 0);
    cudaStreamWaitEvent(side, evFork, 0);
    for (int li = 0; li < 4; ++li) side_w(li);

    for (int li = 0; li < 4; ++li) {
        pack_a_main(li);
        cudaStreamWaitEvent(0, evW[li], 0);
        run_main(li);
    }
}

// round 16
// speedup vs baseline: 1.7141x; 1.1844x over previous
#include <cuda_runtime.h>
#include <cuda_bf16.h>
#include <cstdint>
#include <cstddef>

#define THREADS 512

// Scratch activations (fp32)
__device__ float g_h0[8192u * 2048u];
__device__ float g_h2[8192u * 2048u];

// Packed pre-swizzled bf16 hi/lo weights:
// tw blocks (factorized sw): per (layer, ntile, kchunk64, term 0..3): 32KB
//   term-major k-dim: j = k*64 + il
// bw blocks: per (layer, ntile, kchunk64): 32KB
__device__ __align__(128) char g_swp[104857600];   // 100MB (4/5 used)
__device__ __align__(128) char g_bwp[20971520];    // 20MB
// Packed A-blocks: per (mtile, kchunk64): 5 blocks of 32KB
// blocks 0..3 = phi term tiles (j = k*64 + il), block 4 = x tile.
__device__ __align__(128) char g_ab[402653184];    // 384MB (335MB used)

// M[k][g] = g^k/k! * exp(-2e-4*g^2), k = 0..3 (Taylor = Hermite-optimal here)
__constant__ float TWM[4][8] = {
  {1.0f, 0.99980002f, 0.99920032f, 0.99820162f, 0.99680511f, 0.99501248f, 0.99282590f, 0.99025483f},
  {0.0f, 0.99980002f, 1.99840064f, 2.99460486f, 3.98722045f, 4.97506238f, 5.95695540f, 6.93178379f},
  {0.0f, 0.49990001f, 1.99840064f, 4.49190729f, 7.97444090f, 12.43765595f, 17.87086619f, 24.26124327f},
  {0.0f, 0.16663334f, 1.33226709f, 4.49190729f, 10.63258787f, 20.72942658f, 35.74173238f, 56.60956763f}
};

// ---------------- threefry2x32 (JAX-compatible, validated) ----------------
__device__ __forceinline__ uint32_t rotl32d(uint32_t v, int d) {
    return __funnelshift_l(v, v, d);
}
__device__ __forceinline__ void threefry2x32_dev(uint32_t k0, uint32_t k1,
                                                 uint32_t c0, uint32_t c1,
                                                 uint32_t& o0, uint32_t& o1) {
    uint32_t ks2 = k0 ^ k1 ^ 0x1BD11BDAu;
    uint32_t x0 = c0 + k0, x1 = c1 + k1;
#define TF_RND(r) { x0 += x1; x1 = rotl32d(x1, r); x1 ^= x0; }
    TF_RND(13) TF_RND(15) TF_RND(26) TF_RND(6)
    x0 += k1;  x1 += ks2 + 1u;
    TF_RND(17) TF_RND(29) TF_RND(16) TF_RND(24)
    x0 += ks2; x1 += k0 + 2u;
    TF_RND(13) TF_RND(15) TF_RND(26) TF_RND(6)
    x0 += k0;  x1 += k1 + 3u;
    TF_RND(17) TF_RND(29) TF_RND(16) TF_RND(24)
    x0 += k1;  x1 += ks2 + 4u;
    TF_RND(13) TF_RND(15) TF_RND(26) TF_RND(6)
    x0 += ks2; x1 += k0 + 5u;
#undef TF_RND
    o0 = x0; o1 = x1;
}
static inline uint32_t rotl32h(uint32_t v, int d) {
    return (v << d) | (v >> (32 - d));
}
static void threefry2x32_host(uint32_t k0, uint32_t k1, uint32_t c0, uint32_t c1,
                              uint32_t& o0, uint32_t& o1) {
    uint32_t ks2 = k0 ^ k1 ^ 0x1BD11BDAu;
    uint32_t x0 = c0 + k0, x1 = c1 + k1;
#define TF_RND(r) { x0 += x1; x1 = rotl32h(x1, r); x1 ^= x0; }
    TF_RND(13) TF_RND(15) TF_RND(26) TF_RND(6)
    x0 += k1;  x1 += ks2 + 1u;
    TF_RND(17) TF_RND(29) TF_RND(16) TF_RND(24)
    x0 += ks2; x1 += k0 + 2u;
    TF_RND(13) TF_RND(15) TF_RND(26) TF_RND(6)
    x0 += k0;  x1 += k1 + 3u;
    TF_RND(17) TF_RND(29) TF_RND(16) TF_RND(24)
    x0 += k1;  x1 += ks2 + 4u;
    TF_RND(13) TF_RND(15) TF_RND(26) TF_RND(6)
    x0 += ks2; x1 += k0 + 5u;
#undef TF_RND
    o0 = x0; o1 = x1;
}

// ---------------- helpers ----------------
__device__ __forceinline__ uint32_t smem_u32(const void* p) {
    uint32_t a;
    asm("{ .reg .u64 t; cvta.to.shared.u64 t, %1; cvt.u32.u64 %0, t; }"
        : "=r"(a) : "l"(p));
    return a;
}
#define SW128(o) ((o) ^ ((((uint32_t)(o)) >> 3) & 0x70))

#define LDSM4(rv, a) \
    asm volatile("ldmatrix.sync.aligned.m8n8.x4.shared.b16 {%0,%1,%2,%3}, [%4];" \
        : "=r"((rv)[0]), "=r"((rv)[1]), "=r"((rv)[2]), "=r"((rv)[3]) \
        : "r"(a))

#define MMA_BF16(c, a, b0, b1) \
    asm volatile("mma.sync.aligned.m16n8k16.row.col.f32.bf16.bf16.f32 " \
        "{%0,%1,%2,%3}, {%4,%5,%6,%7}, {%8,%9}, {%0,%1,%2,%3};" \
        : "+f"((c)[0]), "+f"((c)[1]), "+f"((c)[2]), "+f"((c)[3]) \
        : "r"((a)[0]), "r"((a)[1]), "r"((a)[2]), "r"((a)[3]), "r"(b0), "r"(b1))

#define CP_ASYNC16(dst, src) \
    asm volatile("cp.async.cg.shared.global [%0], [%1], 16;" \
                 :: "r"((uint32_t)(dst)), "l"(src) : "memory")
#define CP_COMMIT() asm volatile("cp.async.commit_group;" ::: "memory")
#define CP_WAIT0()  asm volatile("cp.async.wait_group 0;" ::: "memory")
#define CP_WAIT1()  asm volatile("cp.async.wait_group 1;" ::: "memory")

__device__ __forceinline__ void bfsplit2(float a, float b, uint32_t& hi2, uint32_t& lo2) {
    asm("cvt.rn.bf16x2.f32 %0, %1, %2;" : "=r"(hi2) : "f"(b), "f"(a));
    __nv_bfloat162 hv = *reinterpret_cast<__nv_bfloat162*>(&hi2);
    float ra = a - __bfloat162float(hv.x);
    float rb = b - __bfloat162float(hv.y);
    asm("cvt.rn.bf16x2.f32 %0, %1, %2;" : "=r"(lo2) : "f"(rb), "f"(ra));
}

// ---------------- pack kernels ----------------
// tw pack: one thread per (i-pair, o); term-major j = k*64 + il
__global__ void pack_sw_kernel(const float* __restrict__ sw, char* __restrict__ dst,
                               int I, int O) {
    size_t idx = (size_t)blockIdx.x * blockDim.x + threadIdx.x;
    size_t total = (size_t)(I >> 1) * O;
    if (idx >= total) return;
    int o  = (int)(idx % O);
    int ip = (int)(idx / O);
    int i0 = 2 * ip;
    float tw[2][4];
    #pragma unroll
    for (int e = 0; e < 2; ++e) {
        const float4* p = reinterpret_cast<const float4*>(
            &sw[((size_t)(i0 + e) * O + o) * 8]);
        float4 s0 = p[0], s1 = p[1];
        float s[8] = {s0.x, s0.y, s0.z, s0.w, s1.x, s1.y, s1.z, s1.w};
        #pragma unroll
        for (int k = 0; k < 4; ++k) {
            float acc = 0.f;
            #pragma unroll
            for (int g = 0; g < 8; ++g) acc = fmaf(s[g], TWM[k][g], acc);
            tw[e][k] = acc;
        }
    }
    int tn = o >> 7, n = o & 127, kc = i0 >> 6, il0 = i0 & 63;
    const int nkc = I >> 6;
    size_t blkbase = ((size_t)tn * nkc + kc) * 4;
    #pragma unroll
    for (int k = 0; k < 4; ++k) {
        uint32_t hw, lw;
        bfsplit2(tw[0][k], tw[1][k], hw, lw);
        size_t blk = (blkbase + k) * 32768;
        uint32_t off = SW128((uint32_t)(n * 128 + il0 * 2));
        *reinterpret_cast<uint32_t*>(dst + blk + off) = hw;
        *reinterpret_cast<uint32_t*>(dst + blk + 16384 + off) = lw;
    }
}

__global__ void pack_bw_kernel(const float* __restrict__ bw, char* __restrict__ dst,
                               int I, int O) {
    size_t idx = (size_t)blockIdx.x * blockDim.x + threadIdx.x;
    size_t total = (size_t)O * (I >> 1);
    if (idx >= total) return;
    int o = (int)(idx % O);
    int kp = (int)(idx / O);
    float b0 = bw[(size_t)(2 * kp) * O + o];
    float b1 = bw[(size_t)(2 * kp + 1) * O + o];
    uint32_t hw, lw;
    bfsplit2(b0, b1, hw, lw);
    int t = o >> 7, n = o & 127;
    int c = (2 * kp) >> 6, klocal = (2 * kp) & 63;
    size_t blk = ((size_t)t * (I >> 6) + c) * 32768;
    uint32_t off = SW128((uint32_t)(n * 128 + klocal * 2));
    *reinterpret_cast<uint32_t*>(dst + blk + off) = hw;
    *reinterpret_cast<uint32_t*>(dst + blk + 16384 + off) = lw;
}

// phi tiles, term-major: grid (mtiles*nkc*4); thread handles (mloc, il-pair)
__global__ void pack_phi_kernel(const float* __restrict__ act,
                                char* __restrict__ ab, int I, int nkc) {
    int bid = blockIdx.x;
    int s4 = bid & 3;
    int t2 = bid >> 2;
    int kc = t2 % nkc;
    int mt = t2 / nkc;
    char* base = ab + (size_t)(mt * nkc + kc) * 5 * 32768;
    int tid = threadIdx.x;
    #pragma unroll
    for (int rr = 0; rr < 4; ++rr) {
        int v = rr * 256 + tid;          // 1024 (mloc, p) tasks
        int mloc = v >> 3, p = v & 7;
        int ilp = s4 * 8 + p;            // pair index 0..31
        int il0 = ilp * 2;
        float2 xv = *reinterpret_cast<const float2*>(
            &act[(size_t)(mt * 128 + mloc) * I + kc * 64 + il0]);
        float phi[2][4];
        #pragma unroll
        for (int e = 0; e < 2; ++e) {
            float d = (e ? xv.y : xv.x) + 0.044f;
            float E = __expf(-3.125f * d * d);
            float w = 0.05f * d;
            phi[e][0] = E;
            #pragma unroll
            for (int k = 1; k < 4; ++k) phi[e][k] = phi[e][k - 1] * w;
        }
        uint32_t off = SW128((uint32_t)(mloc * 128 + ilp * 4));
        #pragma unroll
        for (int k = 0; k < 4; ++k) {
            uint32_t hw, lw;
            bfsplit2(phi[0][k], phi[1][k], hw, lw);
            *reinterpret_cast<uint32_t*>(base + k * 32768 + off) = hw;
            *reinterpret_cast<uint32_t*>(base + k * 32768 + 16384 + off) = lw;
        }
    }
}

// x tiles (block 4)
__global__ void pack_x_kernel(const float* __restrict__ act,
                              char* __restrict__ ab, int I, int nkc) {
    int bid = blockIdx.x;
    int kc = bid % nkc;
    int mt = bid / nkc;
    char* blk = ab + ((size_t)(mt * nkc + kc) * 5 + 4) * 32768;
    int tid = threadIdx.x;
    #pragma unroll
    for (int rr = 0; rr < 8; ++rr) {
        int v = rr * 256 + tid;
        int mloc = v >> 4, c4 = v & 15;
        float4 xv = *reinterpret_cast<const float4*>(
            &act[(size_t)(mt * 128 + mloc) * I + kc * 64 + c4 * 4]);
        uint32_t h0w, l0w, h1w, l1w;
        bfsplit2(xv.x, xv.y, h0w, l0w);
        bfsplit2(xv.z, xv.w, h1w, l1w);
        uint32_t off = SW128((uint32_t)(mloc * 128 + c4 * 8));
        *reinterpret_cast<uint2*>(blk + off) = make_uint2(h0w, h1w);
        *reinterpret_cast<uint2*>(blk + 16384 + off) = make_uint2(l0w, l1w);
    }
}

// ---------------- SMEM: 3-stage ring, 64KB per stage ----------------
static constexpr int STAGE_STRIDE = 65536;
static constexpr int NSTAGE = 3;
static constexpr int SMEM_SZ = NSTAGE * STAGE_STRIDE;   // 192KB
static constexpr int SMEM_DYN = SMEM_SZ + 1024;

// ---------------- main kernel: R11 mainloop, 5 stages per kchunk --------------
__global__ __launch_bounds__(THREADS, 1)
void kan_mma_kernel(const char* __restrict__ ab,
                    const char* __restrict__ swp,
                    const char* __restrict__ bwp,
                    const float* __restrict__ sbp,
                    const float* __restrict__ ssp,
                    const float* __restrict__ snp,
                    float* __restrict__ outp,
                    int nkc, int O,
                    uint32_t nk0, uint32_t nk1) {
    extern __shared__ char raw[];
    const uint32_t rawu = smem_u32(raw);
    const uint32_t sbase = (rawu + 1023u) & ~1023u;

    const int tid = threadIdx.x;
    const int wid = tid >> 5;
    const int lid = tid & 31;
    const int wm  = wid >> 2;
    const int wn  = wid & 3;
    const int m0  = blockIdx.y * 128;
    const int n0  = blockIdx.x * 128;   // n fastest
    const int mt  = blockIdx.y;

    const int q = lid >> 3, r = lid & 7;
    const int rowA_l = r + (q & 1) * 8;
    const int kselA  = (q >> 1) * 16;
    const int rowB_l = r + (q >> 1) * 8;
    const int kselB  = (q & 1) * 16;

    float accS[2][4][4];
    float accB[2][4][4];
    #pragma unroll
    for (int a = 0; a < 2; ++a)
        #pragma unroll
        for (int b = 0; b < 4; ++b)
            #pragma unroll
            for (int e = 0; e < 4; ++e) { accS[a][b][e] = 0.f; accB[a][b][e] = 0.f; }

    const size_t a_tile = (size_t)mt * nkc;
    const size_t b_tile = (size_t)(n0 >> 7) * nkc;
    const int total = nkc * 5;

    auto issue_stage = [&](int s) {
        int kc = s / 5, sub = s - kc * 5;
        uint32_t dst = sbase + (s % NSTAGE) * STAGE_STRIDE;
        const char* asrc = ab + ((a_tile + kc) * 5 + sub) * 32768;
        const char* bsrc = (sub < 4)
            ? swp + ((b_tile + kc) * 4 + sub) * 32768
            : bwp + (b_tile + kc) * 32768;
        #pragma unroll
        for (int rr = 0; rr < 4; ++rr) {
            uint32_t off = (uint32_t)(rr * THREADS + tid) * 16;
            CP_ASYNC16(dst + off, asrc + off);
        }
        #pragma unroll
        for (int rr = 0; rr < 4; ++rr) {
            uint32_t off = (uint32_t)(rr * THREADS + tid) * 16;
            CP_ASYNC16(dst + 32768 + off, bsrc + off);
        }
        CP_COMMIT();
    };

    auto do_mma = [&](int buf, float (&acc)[2][4][4]) {
        const uint32_t Ah = sbase + buf * STAGE_STRIDE;
        const uint32_t Al = Ah + 16384;
        const uint32_t Bh = Ah + 32768;
        const uint32_t Bl = Ah + 49152;
        #pragma unroll
        for (int k16 = 0; k16 < 4; ++k16) {
            const int kbyt = k16 * 32;
            uint32_t ah[2][4], al[2][4];
            #pragma unroll
            for (int mf = 0; mf < 2; ++mf) {
                int m = wm * 32 + mf * 16 + rowA_l;
                uint32_t off = (uint32_t)(m * 128)
                             + (((uint32_t)(kbyt + kselA)) ^ ((m * 16) & 0x70));
                LDSM4(ah[mf], Ah + off);
                LDSM4(al[mf], Al + off);
            }
            uint32_t bh[2][4], bl[2][4];
            #pragma unroll
            for (int nb = 0; nb < 2; ++nb) {
                int n = wn * 32 + nb * 16 + rowB_l;
                uint32_t off = (uint32_t)(n * 128)
                             + (((uint32_t)(kbyt + kselB)) ^ ((n * 16) & 0x70));
                LDSM4(bh[nb], Bh + off);
                LDSM4(bl[nb], Bl + off);
            }
            #pragma unroll
            for (int mf = 0; mf < 2; ++mf)
                #pragma unroll
                for (int nf = 0; nf < 4; ++nf) {
                    const int nb = nf >> 1, ri = (nf & 1) * 2;
                    MMA_BF16(acc[mf][nf], ah[mf], bh[nb][ri], bh[nb][ri + 1]);
                    MMA_BF16(acc[mf][nf], ah[mf], bl[nb][ri], bl[nb][ri + 1]);
                    MMA_BF16(acc[mf][nf], al[mf], bh[nb][ri], bh[nb][ri + 1]);
                }
        }
    };

    issue_stage(0);
    issue_stage(1);
    for (int s = 0; s < total; ++s) {
        if (s < total - 1) { CP_WAIT1(); } else { CP_WAIT0(); }
        __syncthreads();
        int sub = s % 5;
        if (sub == 4) do_mma(s % NSTAGE, accB);
        else          do_mma(s % NSTAGE, accS);
        if (s + 2 < total) issue_stage(s + 2);
    }

    // ---------------- epilogue ----------------
    const float snv = *snp;
    const int rq = lid >> 2, cq = (lid & 3) * 2;
    #pragma unroll
    for (int mf = 0; mf < 2; ++mf) {
        #pragma unroll
        for (int nf = 0; nf < 4; ++nf) {
            #pragma unroll
            for (int half = 0; half < 2; ++half) {
                int b = m0 + wm * 32 + mf * 16 + rq + half * 8;
                int obase = n0 + wn * 32 + nf * 8 + cq;
                float2 res;
                #pragma unroll
                for (int e = 0; e < 2; ++e) {
                    int o = obase + e;
                    float sv = accS[mf][nf][half * 2 + e];
                    float bv = accB[mf][nf][half * 2 + e];
                    float sg = 1.0f / (1.0f + __expf(-bv));
                    uint32_t li = (uint32_t)b * (uint32_t)O + (uint32_t)o;
                    uint32_t r0, r1;
                    threefry2x32_dev(nk0, nk1, 0u, li, r0, r1);
                    uint32_t bits = r0 ^ r1;
                    float f = __uint_as_float((bits >> 9) | 0x3f800000u) - 1.0f;
                    float uu = fmaxf(-0.99999994f, fmaf(f, 2.0f, -0.99999994f));
                    float nz = 1.41421356f * erfinvf(uu);
                    float val = bv * sg * sbp[o] + sv * ssp[o] + nz * snv;
                    if (e == 0) res.x = val; else res.y = val;
                }
                *reinterpret_cast<float2*>(&outp[(size_t)b * O + obase]) = res;
            }
        }
    }
}

// ---------------- launch (R11/R15 structure) ----------------
extern "C" void kernel_launch(void* const* d_in, const int* in_sizes, int n_in,
                              void* d_out, int out_size) {
    const float* x = (const float*)d_in[0];
    const float* sw[4]; const float* bw[4]; const float* sb[4];
    const float* ss[4]; const float* sn[4];
    for (int li = 0; li < 4; ++li) {
        sw[li] = (const float*)d_in[1 + 5 * li + 0];
        bw[li] = (const float*)d_in[1 + 5 * li + 1];
        sb[li] = (const float*)d_in[1 + 5 * li + 2];
        ss[li] = (const float*)d_in[1 + 5 * li + 3];
        sn[li] = (const float*)d_in[1 + 5 * li + 4];
    }
    const int B = in_sizes[0] / 1024;   // 8192
    float* out  = (float*)d_out;
    float* xrec = out;
    float* z    = out + (size_t)B * 1024;

    float* h0; cudaGetSymbolAddress((void**)&h0, g_h0);
    float* h2; cudaGetSymbolAddress((void**)&h2, g_h2);
    char* swp; cudaGetSymbolAddress((void**)&swp, g_swp);
    char* bwp; cudaGetSymbolAddress((void**)&bwp, g_bwp);
    char* ab;  cudaGetSymbolAddress((void**)&ab, g_ab);

    const int Is[4] = {1024, 2048, 256, 2048};
    const int Os[4] = {2048, 256, 2048, 1024};
    size_t sw_off[4], bw_off[4];
    size_t so = 0, bo = 0;
    for (int li = 0; li < 4; ++li) {
        sw_off[li] = so; bw_off[li] = bo;
        so += (size_t)(Os[li] / 128) * (Is[li] / 64) * 4 * 32768;
        bo += (size_t)(Os[li] / 128) * (Is[li] / 64) * 32768;
    }

    uint32_t fk0[4], fk1[4];
    for (int li = 0; li < 4; ++li)
        threefry2x32_host(0u, 42u, 0u, (uint32_t)li, fk0[li], fk1[li]);

    cudaFuncSetAttribute(kan_mma_kernel,
                         cudaFuncAttributeMaxDynamicSharedMemorySize, SMEM_DYN);

    static cudaStream_t side = [] {
        cudaStream_t s; cudaStreamCreateWithFlags(&s, cudaStreamNonBlocking); return s;
    }();
    static cudaEvent_t evFork = [] {
        cudaEvent_t e; cudaEventCreateWithFlags(&e, cudaEventDisableTiming); return e;
    }();
    static cudaEvent_t evW[4] = {
        [] { cudaEvent_t e; cudaEventCreateWithFlags(&e, cudaEventDisableTiming); return e; }(),
        [] { cudaEvent_t e; cudaEventCreateWithFlags(&e, cudaEventDisableTiming); return e; }(),
        [] { cudaEvent_t e; cudaEventCreateWithFlags(&e, cudaEventDisableTiming); return e; }(),
        [] { cudaEvent_t e; cudaEventCreateWithFlags(&e, cudaEventDisableTiming); return e; }()
    };

    const int mtiles = B / 128;
    dim3 blk(THREADS);
    const float* ins[4]  = {x, h0, z, h2};
    float* outs[4]       = {h0, z, h2, xrec};

    auto side_w = [&](int li) {
        size_t tot = (size_t)(Is[li] / 2) * Os[li];
        pack_sw_kernel<<<(unsigned)((tot + 255) / 256), 256, 0, side>>>(
            sw[li], swp + sw_off[li], Is[li], Os[li]);
        size_t totb = (size_t)Os[li] * (Is[li] / 2);
        pack_bw_kernel<<<(unsigned)((totb + 255) / 256), 256, 0, side>>>(
            bw[li], bwp + bw_off[li], Is[li], Os[li]);
        cudaEventRecord(evW[li], side);
    };
    auto pack_a_main = [&](int li) {
        const int nkc = Is[li] / 64;
        pack_phi_kernel<<<(unsigned)(mtiles * nkc * 4), 256>>>(ins[li], ab, Is[li], nkc);
        pack_x_kernel<<<(unsigned)(mtiles * nkc), 256>>>(ins[li], ab, Is[li], nkc);
    };
    auto run_main = [&](int li) {
        dim3 g(Os[li] / 128, mtiles);
        kan_mma_kernel<<<g, blk, SMEM_DYN>>>(
            ab, swp + sw_off[li], bwp + bw_off[li],
            sb[li], ss[li], sn[li], outs[li],
            Is[li] / 64, Os[li], fk0[li], fk1[li]);
    };

    cudaEventRecord(evFork, 0);
    cudaStreamWaitEvent(side, evFork, 0);
    for (int li = 0; li < 4; ++li) side_w(li);

    for (int li = 0; li < 4; ++li) {
        pack_a_main(li);
        cudaStreamWaitEvent(0, evW[li], 0);
        run_main(li);
    }
}

// round 17
// speedup vs baseline: 1.8258x; 1.0651x over previous
#include <cuda_runtime.h>
#include <cuda_bf16.h>
#include <cstdint>
#include <cstddef>

#define THREADS 256

// Scratch activations (fp32)
__device__ float g_h0[8192u * 2048u];
__device__ float g_h2[8192u * 2048u];

// Packed pre-swizzled bf16 hi/lo weights (layout unchanged from R16):
// tw blocks: per (layer, ntile128, kchunk64, term 0..3): 32KB = [hi 16K | lo 16K]
// bw blocks: per (layer, ntile128, kchunk64): 32KB
__device__ __align__(128) char g_swp[104857600];   // 100MB
__device__ __align__(128) char g_bwp[20971520];    // 20MB
// Packed A-blocks: per (mtile, kchunk64): 5 blocks of 32KB
__device__ __align__(128) char g_ab[402653184];

// M[k][g] = g^k/k! * exp(-2e-4*g^2), k = 0..3
__constant__ float TWM[4][8] = {
  {1.0f, 0.99980002f, 0.99920032f, 0.99820162f, 0.99680511f, 0.99501248f, 0.99282590f, 0.99025483f},
  {0.0f, 0.99980002f, 1.99840064f, 2.99460486f, 3.98722045f, 4.97506238f, 5.95695540f, 6.93178379f},
  {0.0f, 0.49990001f, 1.99840064f, 4.49190729f, 7.97444090f, 12.43765595f, 17.87086619f, 24.26124327f},
  {0.0f, 0.16663334f, 1.33226709f, 4.49190729f, 10.63258787f, 20.72942658f, 35.74173238f, 56.60956763f}
};

// ---------------- threefry2x32 (JAX-compatible, validated) ----------------
__device__ __forceinline__ uint32_t rotl32d(uint32_t v, int d) {
    return __funnelshift_l(v, v, d);
}
__device__ __forceinline__ void threefry2x32_dev(uint32_t k0, uint32_t k1,
                                                 uint32_t c0, uint32_t c1,
                                                 uint32_t& o0, uint32_t& o1) {
    uint32_t ks2 = k0 ^ k1 ^ 0x1BD11BDAu;
    uint32_t x0 = c0 + k0, x1 = c1 + k1;
#define TF_RND(r) { x0 += x1; x1 = rotl32d(x1, r); x1 ^= x0; }
    TF_RND(13) TF_RND(15) TF_RND(26) TF_RND(6)
    x0 += k1;  x1 += ks2 + 1u;
    TF_RND(17) TF_RND(29) TF_RND(16) TF_RND(24)
    x0 += ks2; x1 += k0 + 2u;
    TF_RND(13) TF_RND(15) TF_RND(26) TF_RND(6)
    x0 += k0;  x1 += k1 + 3u;
    TF_RND(17) TF_RND(29) TF_RND(16) TF_RND(24)
    x0 += k1;  x1 += ks2 + 4u;
    TF_RND(13) TF_RND(15) TF_RND(26) TF_RND(6)
    x0 += ks2; x1 += k0 + 5u;
#undef TF_RND
    o0 = x0; o1 = x1;
}
static inline uint32_t rotl32h(uint32_t v, int d) {
    return (v << d) | (v >> (32 - d));
}
static void threefry2x32_host(uint32_t k0, uint32_t k1, uint32_t c0, uint32_t c1,
                              uint32_t& o0, uint32_t& o1) {
    uint32_t ks2 = k0 ^ k1 ^ 0x1BD11BDAu;
    uint32_t x0 = c0 + k0, x1 = c1 + k1;
#define TF_RND(r) { x0 += x1; x1 = rotl32h(x1, r); x1 ^= x0; }
    TF_RND(13) TF_RND(15) TF_RND(26) TF_RND(6)
    x0 += k1;  x1 += ks2 + 1u;
    TF_RND(17) TF_RND(29) TF_RND(16) TF_RND(24)
    x0 += ks2; x1 += k0 + 2u;
    TF_RND(13) TF_RND(15) TF_RND(26) TF_RND(6)
    x0 += k0;  x1 += k1 + 3u;
    TF_RND(17) TF_RND(29) TF_RND(16) TF_RND(24)
    x0 += k1;  x1 += ks2 + 4u;
    TF_RND(13) TF_RND(15) TF_RND(26) TF_RND(6)
    x0 += ks2; x1 += k0 + 5u;
#undef TF_RND
    o0 = x0; o1 = x1;
}

// ---------------- helpers ----------------
__device__ __forceinline__ uint32_t smem_u32(const void* p) {
    uint32_t a;
    asm("{ .reg .u64 t; cvta.to.shared.u64 t, %1; cvt.u32.u64 %0, t; }"
        : "=r"(a) : "l"(p));
    return a;
}
#define SW128(o) ((o) ^ ((((uint32_t)(o)) >> 3) & 0x70))

#define LDSM4(rv, a) \
    asm volatile("ldmatrix.sync.aligned.m8n8.x4.shared.b16 {%0,%1,%2,%3}, [%4];" \
        : "=r"((rv)[0]), "=r"((rv)[1]), "=r"((rv)[2]), "=r"((rv)[3]) \
        : "r"(a))

#define MMA_BF16(c, a, b0, b1) \
    asm volatile("mma.sync.aligned.m16n8k16.row.col.f32.bf16.bf16.f32 " \
        "{%0,%1,%2,%3}, {%4,%5,%6,%7}, {%8,%9}, {%0,%1,%2,%3};" \
        : "+f"((c)[0]), "+f"((c)[1]), "+f"((c)[2]), "+f"((c)[3]) \
        : "r"((a)[0]), "r"((a)[1]), "r"((a)[2]), "r"((a)[3]), "r"(b0), "r"(b1))

#define CP_ASYNC16(dst, src) \
    asm volatile("cp.async.cg.shared.global [%0], [%1], 16;" \
                 :: "r"((uint32_t)(dst)), "l"(src) : "memory")
#define CP_COMMIT() asm volatile("cp.async.commit_group;" ::: "memory")
#define CP_WAIT0()  asm volatile("cp.async.wait_group 0;" ::: "memory")
#define CP_WAIT1()  asm volatile("cp.async.wait_group 1;" ::: "memory")

__device__ __forceinline__ void bfsplit2(float a, float b, uint32_t& hi2, uint32_t& lo2) {
    asm("cvt.rn.bf16x2.f32 %0, %1, %2;" : "=r"(hi2) : "f"(b), "f"(a));
    __nv_bfloat162 hv = *reinterpret_cast<__nv_bfloat162*>(&hi2);
    float ra = a - __bfloat162float(hv.x);
    float rb = b - __bfloat162float(hv.y);
    asm("cvt.rn.bf16x2.f32 %0, %1, %2;" : "=r"(lo2) : "f"(rb), "f"(ra));
}

// ---------------- pack kernels (unchanged from R16) ----------------
__global__ void pack_sw_kernel(const float* __restrict__ sw, char* __restrict__ dst,
                               int I, int O) {
    size_t idx = (size_t)blockIdx.x * blockDim.x + threadIdx.x;
    size_t total = (size_t)(I >> 1) * O;
    if (idx >= total) return;
    int o  = (int)(idx % O);
    int ip = (int)(idx / O);
    int i0 = 2 * ip;
    float tw[2][4];
    #pragma unroll
    for (int e = 0; e < 2; ++e) {
        const float4* p = reinterpret_cast<const float4*>(
            &sw[((size_t)(i0 + e) * O + o) * 8]);
        float4 s0 = p[0], s1 = p[1];
        float s[8] = {s0.x, s0.y, s0.z, s0.w, s1.x, s1.y, s1.z, s1.w};
        #pragma unroll
        for (int k = 0; k < 4; ++k) {
            float acc = 0.f;
            #pragma unroll
            for (int g = 0; g < 8; ++g) acc = fmaf(s[g], TWM[k][g], acc);
            tw[e][k] = acc;
        }
    }
    int tn = o >> 7, n = o & 127, kc = i0 >> 6, il0 = i0 & 63;
    const int nkc = I >> 6;
    size_t blkbase = ((size_t)tn * nkc + kc) * 4;
    #pragma unroll
    for (int k = 0; k < 4; ++k) {
        uint32_t hw, lw;
        bfsplit2(tw[0][k], tw[1][k], hw, lw);
        size_t blk = (blkbase + k) * 32768;
        uint32_t off = SW128((uint32_t)(n * 128 + il0 * 2));
        *reinterpret_cast<uint32_t*>(dst + blk + off) = hw;
        *reinterpret_cast<uint32_t*>(dst + blk + 16384 + off) = lw;
    }
}

__global__ void pack_bw_kernel(const float* __restrict__ bw, char* __restrict__ dst,
                               int I, int O) {
    size_t idx = (size_t)blockIdx.x * blockDim.x + threadIdx.x;
    size_t total = (size_t)O * (I >> 1);
    if (idx >= total) return;
    int o = (int)(idx % O);
    int kp = (int)(idx / O);
    float b0 = bw[(size_t)(2 * kp) * O + o];
    float b1 = bw[(size_t)(2 * kp + 1) * O + o];
    uint32_t hw, lw;
    bfsplit2(b0, b1, hw, lw);
    int t = o >> 7, n = o & 127;
    int c = (2 * kp) >> 6, klocal = (2 * kp) & 63;
    size_t blk = ((size_t)t * (I >> 6) + c) * 32768;
    uint32_t off = SW128((uint32_t)(n * 128 + klocal * 2));
    *reinterpret_cast<uint32_t*>(dst + blk + off) = hw;
    *reinterpret_cast<uint32_t*>(dst + blk + 16384 + off) = lw;
}

__global__ void pack_phi_kernel(const float* __restrict__ act,
                                char* __restrict__ ab, int I, int nkc) {
    int bid = blockIdx.x;
    int s4 = bid & 3;
    int t2 = bid >> 2;
    int kc = t2 % nkc;
    int mt = t2 / nkc;
    char* base = ab + (size_t)(mt * nkc + kc) * 5 * 32768;
    int tid = threadIdx.x;
    #pragma unroll
    for (int rr = 0; rr < 4; ++rr) {
        int v = rr * 256 + tid;
        int mloc = v >> 3, p = v & 7;
        int ilp = s4 * 8 + p;
        int il0 = ilp * 2;
        float2 xv = *reinterpret_cast<const float2*>(
            &act[(size_t)(mt * 128 + mloc) * I + kc * 64 + il0]);
        float phi[2][4];
        #pragma unroll
        for (int e = 0; e < 2; ++e) {
            float d = (e ? xv.y : xv.x) + 0.044f;
            float E = __expf(-3.125f * d * d);
            float w = 0.05f * d;
            phi[e][0] = E;
            #pragma unroll
            for (int k = 1; k < 4; ++k) phi[e][k] = phi[e][k - 1] * w;
        }
        uint32_t off = SW128((uint32_t)(mloc * 128 + ilp * 4));
        #pragma unroll
        for (int k = 0; k < 4; ++k) {
            uint32_t hw, lw;
            bfsplit2(phi[0][k], phi[1][k], hw, lw);
            *reinterpret_cast<uint32_t*>(base + k * 32768 + off) = hw;
            *reinterpret_cast<uint32_t*>(base + k * 32768 + 16384 + off) = lw;
        }
    }
}

__global__ void pack_x_kernel(const float* __restrict__ act,
                              char* __restrict__ ab, int I, int nkc) {
    int bid = blockIdx.x;
    int kc = bid % nkc;
    int mt = bid / nkc;
    char* blk = ab + ((size_t)(mt * nkc + kc) * 5 + 4) * 32768;
    int tid = threadIdx.x;
    #pragma unroll
    for (int rr = 0; rr < 8; ++rr) {
        int v = rr * 256 + tid;
        int mloc = v >> 4, c4 = v & 15;
        float4 xv = *reinterpret_cast<const float4*>(
            &act[(size_t)(mt * 128 + mloc) * I + kc * 64 + c4 * 4]);
        uint32_t h0w, l0w, h1w, l1w;
        bfsplit2(xv.x, xv.y, h0w, l0w);
        bfsplit2(xv.z, xv.w, h1w, l1w);
        uint32_t off = SW128((uint32_t)(mloc * 128 + c4 * 8));
        *reinterpret_cast<uint2*>(blk + off) = make_uint2(h0w, h1w);
        *reinterpret_cast<uint2*>(blk + 16384 + off) = make_uint2(l0w, l1w);
    }
}

// ---------------- SMEM: 2-stage ring, 48KB per stage, 2 CTAs/SM --------------
// stage: A_hi(16K) | A_lo(16K) | B_hi(8K) | B_lo(8K)
static constexpr int STAGE_STRIDE = 49152;
static constexpr int NSTAGE = 2;
static constexpr int SMEM_SZ = NSTAGE * STAGE_STRIDE;   // 96KB
static constexpr int SMEM_DYN = SMEM_SZ + 1024;

// ---------------- main kernel: 128x64 tile, 8 warps, 2 CTAs/SM ----------------
__global__ __launch_bounds__(THREADS, 2)
void kan_mma_kernel(const char* __restrict__ ab,
                    const char* __restrict__ swp,
                    const char* __restrict__ bwp,
                    const float* __restrict__ sbp,
                    const float* __restrict__ ssp,
                    const float* __restrict__ snp,
                    float* __restrict__ outp,
                    int nkc, int O,
                    uint32_t nk0, uint32_t nk1) {
    extern __shared__ char raw[];
    const uint32_t rawu = smem_u32(raw);
    const uint32_t sbase = (rawu + 1023u) & ~1023u;

    const int tid = threadIdx.x;
    const int wid = tid >> 5;
    const int lid = tid & 31;
    const int wm  = wid >> 1;       // 0..3 (32 m rows each)
    const int wn  = wid & 1;        // 0..1 (32 n cols each)
    const int m0  = blockIdx.y * 128;
    const int n0  = blockIdx.x * 64;    // N=64 tiles, n fastest
    const int mt  = blockIdx.y;
    const uint32_t bsel = ((uint32_t)n0 >> 6) & 1;   // which half of packed B block

    const int q = lid >> 3, r = lid & 7;
    const int rowA_l = r + (q & 1) * 8;
    const int kselA  = (q >> 1) * 16;
    const int rowB_l = r + (q >> 1) * 8;
    const int kselB  = (q & 1) * 16;

    float accS[2][4][4];
    float accB[2][4][4];
    #pragma unroll
    for (int a = 0; a < 2; ++a)
        #pragma unroll
        for (int b = 0; b < 4; ++b)
            #pragma unroll
            for (int e = 0; e < 4; ++e) { accS[a][b][e] = 0.f; accB[a][b][e] = 0.f; }

    const size_t a_tile = (size_t)mt * nkc;
    const size_t b_tile = (size_t)(n0 >> 7) * nkc;
    const int total = nkc * 5;

    auto issue_stage = [&](int s) {
        int kc = s / 5, sub = s - kc * 5;
        uint32_t dst = sbase + (s & 1) * STAGE_STRIDE;
        const char* asrc = ab + ((a_tile + kc) * 5 + sub) * 32768;
        const char* bblk = (sub < 4)
            ? swp + ((b_tile + kc) * 4 + sub) * 32768
            : bwp + (b_tile + kc) * 32768;
        // A: 32KB (hi+lo contiguous)
        #pragma unroll
        for (int rr = 0; rr < 8; ++rr) {
            uint32_t off = (uint32_t)(rr * THREADS + tid) * 16;
            CP_ASYNC16(dst + off, asrc + off);
        }
        // B hi: 8KB half selected by bsel
        #pragma unroll
        for (int rr = 0; rr < 2; ++rr) {
            uint32_t off = (uint32_t)(rr * THREADS + tid) * 16;
            CP_ASYNC16(dst + 32768 + off, bblk + bsel * 8192 + off);
        }
        // B lo: 8KB
        #pragma unroll
        for (int rr = 0; rr < 2; ++rr) {
            uint32_t off = (uint32_t)(rr * THREADS + tid) * 16;
            CP_ASYNC16(dst + 40960 + off, bblk + 16384 + bsel * 8192 + off);
        }
        CP_COMMIT();
    };

    auto do_mma = [&](int buf, float (&acc)[2][4][4]) {
        const uint32_t Ah = sbase + buf * STAGE_STRIDE;
        const uint32_t Al = Ah + 16384;
        const uint32_t Bh = Ah + 32768;
        const uint32_t Bl = Ah + 40960;
        #pragma unroll
        for (int k16 = 0; k16 < 4; ++k16) {
            const int kbyt = k16 * 32;
            uint32_t ah[2][4], al[2][4];
            #pragma unroll
            for (int mf = 0; mf < 2; ++mf) {
                int m = wm * 32 + mf * 16 + rowA_l;
                uint32_t off = (uint32_t)(m * 128)
                             + (((uint32_t)(kbyt + kselA)) ^ ((m * 16) & 0x70));
                LDSM4(ah[mf], Ah + off);
                LDSM4(al[mf], Al + off);
            }
            uint32_t bh[2][4], bl[2][4];
            #pragma unroll
            for (int nb = 0; nb < 2; ++nb) {
                int n = wn * 32 + nb * 16 + rowB_l;   // local n within 64
                uint32_t off = (uint32_t)(n * 128)
                             + (((uint32_t)(kbyt + kselB)) ^ ((n * 16) & 0x70));
                LDSM4(bh[nb], Bh + off);
                LDSM4(bl[nb], Bl + off);
            }
            #pragma unroll
            for (int mf = 0; mf < 2; ++mf)
                #pragma unroll
                for (int nf = 0; nf < 4; ++nf) {
                    const int nb = nf >> 1, ri = (nf & 1) * 2;
                    MMA_BF16(acc[mf][nf], ah[mf], bh[nb][ri], bh[nb][ri + 1]);
                    MMA_BF16(acc[mf][nf], ah[mf], bl[nb][ri], bl[nb][ri + 1]);
                    MMA_BF16(acc[mf][nf], al[mf], bh[nb][ri], bh[nb][ri + 1]);
                }
        }
    };

    issue_stage(0);
    for (int s = 0; s < total; ++s) {
        if (s + 1 < total) issue_stage(s + 1);   // prefetch into other buffer
        if (s + 1 < total) { CP_WAIT1(); } else { CP_WAIT0(); }
        __syncthreads();
        int sub = s % 5;
        if (sub == 4) do_mma(s & 1, accB);
        else          do_mma(s & 1, accS);
        __syncthreads();   // all warps done with buf before it is refilled next iter
    }

    // ---------------- epilogue ----------------
    const float snv = *snp;
    const int rq = lid >> 2, cq = (lid & 3) * 2;
    #pragma unroll
    for (int mf = 0; mf < 2; ++mf) {
        #pragma unroll
        for (int nf = 0; nf < 4; ++nf) {
            #pragma unroll
            for (int half = 0; half < 2; ++half) {
                int b = m0 + wm * 32 + mf * 16 + rq + half * 8;
                int obase = n0 + wn * 32 + nf * 8 + cq;
                float2 res;
                #pragma unroll
                for (int e = 0; e < 2; ++e) {
                    int o = obase + e;
                    float sv = accS[mf][nf][half * 2 + e];
                    float bv = accB[mf][nf][half * 2 + e];
                    float sg = 1.0f / (1.0f + __expf(-bv));
                    uint32_t li = (uint32_t)b * (uint32_t)O + (uint32_t)o;
                    uint32_t r0, r1;
                    threefry2x32_dev(nk0, nk1, 0u, li, r0, r1);
                    uint32_t bits = r0 ^ r1;
                    float f = __uint_as_float((bits >> 9) | 0x3f800000u) - 1.0f;
                    float uu = fmaxf(-0.99999994f, fmaf(f, 2.0f, -0.99999994f));
                    float nz = 1.41421356f * erfinvf(uu);
                    float val = bv * sg * sbp[o] + sv * ssp[o] + nz * snv;
                    if (e == 0) res.x = val; else res.y = val;
                }
                *reinterpret_cast<float2*>(&outp[(size_t)b * O + obase]) = res;
            }
        }
    }
}

// ---------------- launch (R16 structure, N=64 grid) ----------------
extern "C" void kernel_launch(void* const* d_in, const int* in_sizes, int n_in,
                              void* d_out, int out_size) {
    const float* x = (const float*)d_in[0];
    const float* sw[4]; const float* bw[4]; const float* sb[4];
    const float* ss[4]; const float* sn[4];
    for (int li = 0; li < 4; ++li) {
        sw[li] = (const float*)d_in[1 + 5 * li + 0];
        bw[li] = (const float*)d_in[1 + 5 * li + 1];
        sb[li] = (const float*)d_in[1 + 5 * li + 2];
        ss[li] = (const float*)d_in[1 + 5 * li + 3];
        sn[li] = (const float*)d_in[1 + 5 * li + 4];
    }
    const int B = in_sizes[0] / 1024;   // 8192
    float* out  = (float*)d_out;
    float* xrec = out;
    float* z    = out + (size_t)B * 1024;

    float* h0; cudaGetSymbolAddress((void**)&h0, g_h0);
    float* h2; cudaGetSymbolAddress((void**)&h2, g_h2);
    char* swp; cudaGetSymbolAddress((void**)&swp, g_swp);
    char* bwp; cudaGetSymbolAddress((void**)&bwp, g_bwp);
    char* ab;  cudaGetSymbolAddress((void**)&ab, g_ab);

    const int Is[4] = {1024, 2048, 256, 2048};
    const int Os[4] = {2048, 256, 2048, 1024};
    size_t sw_off[4], bw_off[4];
    size_t so = 0, bo = 0;
    for (int li = 0; li < 4; ++li) {
        sw_off[li] = so; bw_off[li] = bo;
        so += (size_t)(Os[li] / 128) * (Is[li] / 64) * 4 * 32768;
        bo += (size_t)(Os[li] / 128) * (Is[li] / 64) * 32768;
    }

    uint32_t fk0[4], fk1[4];
    for (int li = 0; li < 4; ++li)
        threefry2x32_host(0u, 42u, 0u, (uint32_t)li, fk0[li], fk1[li]);

    cudaFuncSetAttribute(kan_mma_kernel,
                         cudaFuncAttributeMaxDynamicSharedMemorySize, SMEM_DYN);

    static cudaStream_t side = [] {
        cudaStream_t s; cudaStreamCreateWithFlags(&s, cudaStreamNonBlocking); return s;
    }();
    static cudaEvent_t evFork = [] {
        cudaEvent_t e; cudaEventCreateWithFlags(&e, cudaEventDisableTiming); return e;
    }();
    static cudaEvent_t evW[4] = {
        [] { cudaEvent_t e; cudaEventCreateWithFlags(&e, cudaEventDisableTiming); return e; }(),
        [] { cudaEvent_t e; cudaEventCreateWithFlags(&e, cudaEventDisableTiming); return e; }(),
        [] { cudaEvent_t e; cudaEventCreateWithFlags(&e, cudaEventDisableTiming); return e; }(),
        [] { cudaEvent_t e; cudaEventCreateWithFlags(&e, cudaEventDisableTiming); return e; }()
    };

    const int mtiles = B / 128;
    dim3 blk(THREADS);
    const float* ins[4]  = {x, h0, z, h2};
    float* outs[4]       = {h0, z, h2, xrec};

    auto side_w = [&](int li) {
        size_t tot = (size_t)(Is[li] / 2) * Os[li];
        pack_sw_kernel<<<(unsigned)((tot + 255) / 256), 256, 0, side>>>(
            sw[li], swp + sw_off[li], Is[li], Os[li]);
        size_t totb = (size_t)Os[li] * (Is[li] / 2);
        pack_bw_kernel<<<(unsigned)((totb + 255) / 256), 256, 0, side>>>(
            bw[li], bwp + bw_off[li], Is[li], Os[li]);
        cudaEventRecord(evW[li], side);
    };
    auto pack_a_main = [&](int li) {
        const int nkc = Is[li] / 64;
        pack_phi_kernel<<<(unsigned)(mtiles * nkc * 4), 256>>>(ins[li], ab, Is[li], nkc);
        pack_x_kernel<<<(unsigned)(mtiles * nkc), 256>>>(ins[li], ab, Is[li], nkc);
    };
    auto run_main = [&](int li) {
        dim3 g(Os[li] / 64, mtiles);   // N=64 tiles
        kan_mma_kernel<<<g, blk, SMEM_DYN>>>(
            ab, swp + sw_off[li], bwp + bw_off[li],
            sb[li], ss[li], sn[li], outs[li],
            Is[li] / 64, Os[li], fk0[li], fk1[li]);
    };

    cudaEventRecord(evFork, 0);
    cudaStreamWaitEvent(side, evFork, 0);
    for (int li = 0; li < 4; ++li) side_w(li);

    for (int li = 0; li < 4; ++li) {
        pack_a_main(li);
        cudaStreamWaitEvent(0, evW[li], 0);
        run_main(li);
    }
}